// round 13
// baseline (speedup 1.0000x reference)
#include <cuda_runtime.h>
#include <cuda_bf16.h>
#include <math.h>
#include <stdint.h>

typedef __nv_bfloat16 bf16;

// ---------------------------------------------------------------------------
// Problem constants
// ---------------------------------------------------------------------------
#define BB 4
#define LL 1024
#define DD 1024
#define HH 16
#define HD 64
#define II 3280
#define I2 6560
#define I2P 6656               // I2 padded to 128
#define IKP 3328               // II padded to 128 (w2 K / g stride)
#define QKVD 3072
#define NROWS (BB * LL)        // 4096
#define EPSV 1e-5f

#define SZ_D ((size_t)NROWS * DD)

// fp32 scratch: qkv(3*SZ_D), a, h, f
__device__ float g_scratch[6 * SZ_D];
__device__ float g_bias_qkv[QKVD];
__device__ float g_bias_ffn[I2P];

// bf16 scratch (hi/lo pairs)
#define BSZ_ACT ((size_t)NROWS * DD)
#define BSZ_G   ((size_t)NROWS * IKP)
#define BSZ_W   ((size_t)I2P * 1024)
__device__ bf16 g_bscratch[6 * BSZ_ACT + 2 * BSZ_G + 2 * BSZ_W];

// ---------------------------------------------------------------------------
// helpers
// ---------------------------------------------------------------------------
__device__ __forceinline__ void split_f32(float v, bf16& hi, bf16& lo) {
    hi = __float2bfloat16(v);
    lo = __float2bfloat16(v - __bfloat162float(hi));
}

__device__ __forceinline__ void cpa16p(bf16* dst, const bf16* src, bool valid) {
    uint32_t d = (uint32_t)__cvta_generic_to_shared(dst);
    int sz = valid ? 16 : 0;
    asm volatile("cp.async.ca.shared.global [%0], [%1], 16, %2;\n"
                 :: "r"(d), "l"(src), "r"(sz));
}
__device__ __forceinline__ void cpa_commit() {
    asm volatile("cp.async.commit_group;\n" ::: "memory");
}
__device__ __forceinline__ void cpa_wait_all() {
    asm volatile("cp.async.wait_group 0;\n" ::: "memory");
}

__device__ __forceinline__ void ldm4(uint32_t* r, uint32_t addr) {
    asm volatile("ldmatrix.sync.aligned.m8n8.x4.shared.b16 {%0,%1,%2,%3}, [%4];\n"
                 : "=r"(r[0]), "=r"(r[1]), "=r"(r[2]), "=r"(r[3]) : "r"(addr));
}

__device__ __forceinline__ void mma16816(float* d, const uint32_t* a, const uint32_t* b) {
    asm volatile(
        "mma.sync.aligned.m16n8k16.row.col.f32.bf16.bf16.f32 "
        "{%0,%1,%2,%3}, {%4,%5,%6,%7}, {%8,%9}, {%0,%1,%2,%3};\n"
        : "+f"(d[0]), "+f"(d[1]), "+f"(d[2]), "+f"(d[3])
        : "r"(a[0]), "r"(a[1]), "r"(a[2]), "r"(a[3]), "r"(b[0]), "r"(b[1]));
}

__device__ __forceinline__ void store_split8(bf16* hi, bf16* lo, const float* v) {
    bf16 hbuf[8], lbuf[8];
#pragma unroll
    for (int i = 0; i < 8; i++) split_f32(v[i], hbuf[i], lbuf[i]);
    *(uint4*)hi = *(const uint4*)hbuf;
    *(uint4*)lo = *(const uint4*)lbuf;
}

// ---------------------------------------------------------------------------
// RMSNorm (fp32 out, optional residual)
// ---------------------------------------------------------------------------
template <int W, int T>
__global__ void rmsnorm_k(const float* __restrict__ in,
                          const float* __restrict__ w,
                          const float* __restrict__ resid,
                          float* __restrict__ out)
{
    constexpr int PER = W / T;
    const size_t row = blockIdx.x;
    const float* xr = in + row * (size_t)W;
    float vals[PER];
    float ss = 0.f;
#pragma unroll
    for (int i = 0; i < PER; i++) {
        float vv = xr[threadIdx.x + i * T];
        vv = fminf(fmaxf(vv, -10000.f), 10000.f);
        vals[i] = vv;
        ss += vv * vv;
    }
    __shared__ float red[T];
    red[threadIdx.x] = ss;
    __syncthreads();
#pragma unroll
    for (int s = T / 2; s > 0; s >>= 1) {
        if (threadIdx.x < s) red[threadIdx.x] += red[threadIdx.x + s];
        __syncthreads();
    }
    const float mean = red[0] / (float)W;
    const float inv = 1.f / sqrtf(fmaxf(mean, EPSV) + EPSV);
#pragma unroll
    for (int i = 0; i < PER; i++) {
        const int c = threadIdx.x + i * T;
        float o = vals[i] * inv * w[c];
        if (!isfinite(o)) o = 0.f;
        if (resid) o += resid[row * (size_t)W + c];
        out[row * (size_t)W + c] = o;
    }
}

// RMSNorm writing bf16 hi/lo split
template <int W, int T>
__global__ void rmsnorm_split_k(const float* __restrict__ in,
                                const float* __restrict__ w,
                                bf16* __restrict__ ohi,
                                bf16* __restrict__ olo)
{
    constexpr int PER = W / T;
    const size_t row = blockIdx.x;
    const float* xr = in + row * (size_t)W;
    float vals[PER];
    float ss = 0.f;
#pragma unroll
    for (int i = 0; i < PER; i++) {
        float vv = xr[threadIdx.x + i * T];
        vv = fminf(fmaxf(vv, -10000.f), 10000.f);
        vals[i] = vv;
        ss += vv * vv;
    }
    __shared__ float red[T];
    red[threadIdx.x] = ss;
    __syncthreads();
#pragma unroll
    for (int s = T / 2; s > 0; s >>= 1) {
        if (threadIdx.x < s) red[threadIdx.x] += red[threadIdx.x + s];
        __syncthreads();
    }
    const float mean = red[0] / (float)W;
    const float inv = 1.f / sqrtf(fmaxf(mean, EPSV) + EPSV);
#pragma unroll
    for (int i = 0; i < PER; i++) {
        const int c = threadIdx.x + i * T;
        float o = vals[i] * inv * w[c];
        if (!isfinite(o)) o = 0.f;
        bf16 hi, lo;
        split_f32(o, hi, lo);
        ohi[row * (size_t)W + c] = hi;
        olo[row * (size_t)W + c] = lo;
    }
}

// ---------------------------------------------------------------------------
// Vectorized weight split (8 elems/thread)
// ---------------------------------------------------------------------------
__global__ void conv_split8_k(const float* __restrict__ src,
                              bf16* __restrict__ hi, bf16* __restrict__ lo,
                              int rows, int K0, int rowsPad, int KP)
{
    size_t i8 = ((size_t)blockIdx.x * blockDim.x + threadIdx.x) * 8;
    size_t n = (size_t)rowsPad * KP;
    if (i8 >= n) return;
    int r = (int)(i8 / KP);
    int c = (int)(i8 % KP);
    float v[8];
    if (r < rows && c + 8 <= K0) {
        const float* s = src + (size_t)r * K0 + c;
        *(float4*)&v[0] = *(const float4*)s;
        *(float4*)&v[4] = *(const float4*)(s + 4);
    } else {
#pragma unroll
        for (int i = 0; i < 8; i++) {
            int cc = c + i;
            v[i] = (r < rows && cc < K0) ? src[(size_t)r * K0 + cc] : 0.f;
        }
    }
    store_split8(hi + i8, lo + i8, v);
}

// Interleaved w1/w3 split
__global__ void conv_split_ilv8_k(const float* __restrict__ w1,
                                  const float* __restrict__ w3,
                                  bf16* __restrict__ hi, bf16* __restrict__ lo)
{
    size_t i8 = ((size_t)blockIdx.x * blockDim.x + threadIdx.x) * 8;
    size_t n = (size_t)I2P * DD;
    if (i8 >= n) return;
    int r = (int)(i8 / DD);
    int c = (int)(i8 % DD);
    int sr = r >> 1;
    float v[8];
    if (sr < II) {
        const float* s = ((r & 1) ? w3 : w1) + (size_t)sr * DD + c;
        *(float4*)&v[0] = *(const float4*)s;
        *(float4*)&v[4] = *(const float4*)(s + 4);
    } else {
#pragma unroll
        for (int i = 0; i < 8; i++) v[i] = 0.f;
    }
    store_split8(hi + i8, lo + i8, v);
}

// bias concat
__global__ void bias_concat_k(const float* qb, const float* kb, const float* vb,
                              const float* b1, const float* b3,
                              float* outQKV, float* outFFN)
{
    int i = blockIdx.x * blockDim.x + threadIdx.x;
    if (i < 1024) {
        outQKV[i] = qb[i];
        outQKV[1024 + i] = kb[i];
        outQKV[2048 + i] = vb[i];
    }
    if (i < I2P) {
        int sr = i >> 1;
        outFFN[i] = (sr < II) ? ((i & 1) ? b3[sr] : b1[sr]) : 0.f;
    }
}

// ---------------------------------------------------------------------------
// bf16x3 tensor-core GEMM (NT) — proven R9 config: CTA 128x128, BK=32,
// 256 threads (8 warps 2x4, 64x32/warp), cp.async double-buffer, SKT=40.
// fuse_silu: interleaved (z1,z3) cols -> g=silu(z1)*z3 bf16 hi/lo split out.
// ---------------------------------------------------------------------------
#define SKT 40
#define STAGE_ELEMS (128 * SKT)
#define GEMM_SMEM (2 * 4 * STAGE_ELEMS * 2)        // 81920 bytes

__global__ void __launch_bounds__(256)
gemm_bf16x3(const bf16* __restrict__ Ah, const bf16* __restrict__ Al,
            const bf16* __restrict__ Bh, const bf16* __restrict__ Bl,
            const float* __restrict__ bias, float* __restrict__ C,
            int Mtot, int K, int ldc,
            int fuse_silu, bf16* __restrict__ Ghi, bf16* __restrict__ Glo,
            int ldg)
{
    extern __shared__ __align__(16) bf16 smem[];

    const int tid = threadIdx.x;
    const int lane = tid & 31;
    const int wid = tid >> 5;
    const int wm = wid & 1;
    const int wn = wid >> 1;

    const int bm = blockIdx.x * 128;
    const int bn = blockIdx.y * 128;

    const int ldr = tid >> 1;
    const int ldcol = (tid & 1) * 16;

    const bf16* gAh = Ah + (size_t)(bn + ldr) * K + ldcol;
    const bf16* gAl = Al + (size_t)(bn + ldr) * K + ldcol;
    const bool bvalid = (bm + ldr) < Mtot;
    const bf16* gBh = Bh + (size_t)(bm + ldr) * K + ldcol;
    const bf16* gBl = Bl + (size_t)(bm + ldr) * K + ldcol;

    const int s_off = ldr * SKT + ldcol;

    float acc[4][4][4];
#pragma unroll
    for (int i = 0; i < 4; i++)
#pragma unroll
        for (int j = 0; j < 4; j++)
#pragma unroll
            for (int r = 0; r < 4; r++) acc[i][j][r] = 0.f;

    const int nk = K >> 5;

    {
        bf16* s = smem;
        cpa16p(s + 0 * STAGE_ELEMS + s_off,     gAh,     true);
        cpa16p(s + 0 * STAGE_ELEMS + s_off + 8, gAh + 8, true);
        cpa16p(s + 1 * STAGE_ELEMS + s_off,     gAl,     true);
        cpa16p(s + 1 * STAGE_ELEMS + s_off + 8, gAl + 8, true);
        cpa16p(s + 2 * STAGE_ELEMS + s_off,     gBh,     bvalid);
        cpa16p(s + 2 * STAGE_ELEMS + s_off + 8, gBh + 8, bvalid);
        cpa16p(s + 3 * STAGE_ELEMS + s_off,     gBl,     bvalid);
        cpa16p(s + 3 * STAGE_ELEMS + s_off + 8, gBl + 8, bvalid);
    }
    cpa_commit();

    const int a_row = wm * 64 + (lane & 15);
    const int a_colsel = ((lane >> 4) & 1) << 3;
    const int b_row0 = wn * 32 + (((lane >> 4) & 1) << 3) + (lane & 7);
    const int b_colsel = ((lane >> 3) & 1) << 3;

    for (int kt = 0; kt < nk; kt++) {
        cpa_wait_all();
        __syncthreads();

        if (kt + 1 < nk) {
            bf16* s = smem + ((kt + 1) & 1) * (4 * STAGE_ELEMS);
            const int ko = (kt + 1) << 5;
            cpa16p(s + 0 * STAGE_ELEMS + s_off,     gAh + ko,     true);
            cpa16p(s + 0 * STAGE_ELEMS + s_off + 8, gAh + ko + 8, true);
            cpa16p(s + 1 * STAGE_ELEMS + s_off,     gAl + ko,     true);
            cpa16p(s + 1 * STAGE_ELEMS + s_off + 8, gAl + ko + 8, true);
            cpa16p(s + 2 * STAGE_ELEMS + s_off,     gBh + ko,     bvalid);
            cpa16p(s + 2 * STAGE_ELEMS + s_off + 8, gBh + ko + 8, bvalid);
            cpa16p(s + 3 * STAGE_ELEMS + s_off,     gBl + ko,     bvalid);
            cpa16p(s + 3 * STAGE_ELEMS + s_off + 8, gBl + ko + 8, bvalid);
        }
        cpa_commit();

        bf16* st = smem + (kt & 1) * (4 * STAGE_ELEMS);
        const uint32_t sAh = (uint32_t)__cvta_generic_to_shared(st + 0 * STAGE_ELEMS);
        const uint32_t sAl = (uint32_t)__cvta_generic_to_shared(st + 1 * STAGE_ELEMS);
        const uint32_t sBh = (uint32_t)__cvta_generic_to_shared(st + 2 * STAGE_ELEMS);
        const uint32_t sBl = (uint32_t)__cvta_generic_to_shared(st + 3 * STAGE_ELEMS);

#pragma unroll
        for (int ks = 0; ks < 2; ks++) {
            const int koff = ks * 16;
            uint32_t ah[4][4], al[4][4], bh[4][2], bl[4][2];
#pragma unroll
            for (int mi = 0; mi < 4; mi++) {
                const uint32_t off =
                    ((a_row + mi * 16) * SKT + koff + a_colsel) * 2;
                ldm4(ah[mi], sAh + off);
                ldm4(al[mi], sAl + off);
            }
#pragma unroll
            for (int p = 0; p < 2; p++) {
                const uint32_t off =
                    ((b_row0 + p * 16) * SKT + koff + b_colsel) * 2;
                uint32_t th[4], tl[4];
                ldm4(th, sBh + off);
                ldm4(tl, sBl + off);
                bh[p * 2][0] = th[0]; bh[p * 2][1] = th[1];
                bh[p * 2 + 1][0] = th[2]; bh[p * 2 + 1][1] = th[3];
                bl[p * 2][0] = tl[0]; bl[p * 2][1] = tl[1];
                bl[p * 2 + 1][0] = tl[2]; bl[p * 2 + 1][1] = tl[3];
            }
#pragma unroll
            for (int mi = 0; mi < 4; mi++)
#pragma unroll
                for (int ni = 0; ni < 4; ni++) {
                    mma16816(acc[mi][ni], ah[mi], bh[ni]);
                    mma16816(acc[mi][ni], ah[mi], bl[ni]);
                    mma16816(acc[mi][ni], al[mi], bh[ni]);
                }
        }
        __syncthreads();
    }

    const int trow = lane >> 2;
    const int tcol = (lane & 3) * 2;
    if (!fuse_silu) {
#pragma unroll
        for (int mi = 0; mi < 4; mi++) {
            const size_t r0 = (size_t)bn + wm * 64 + mi * 16 + trow;
#pragma unroll
            for (int ni = 0; ni < 4; ni++) {
                const int col = bm + wn * 32 + ni * 8 + tcol;
                if (col < Mtot) {
                    const float b0 = bias[col];
                    const float b1 = bias[col + 1];
                    float2 v0 = make_float2(acc[mi][ni][0] + b0, acc[mi][ni][1] + b1);
                    float2 v1 = make_float2(acc[mi][ni][2] + b0, acc[mi][ni][3] + b1);
                    *(float2*)&C[r0 * (size_t)ldc + col] = v0;
                    *(float2*)&C[(r0 + 8) * (size_t)ldc + col] = v1;
                }
            }
        }
    } else {
#pragma unroll
        for (int mi = 0; mi < 4; mi++) {
            const size_t r0 = (size_t)bn + wm * 64 + mi * 16 + trow;
#pragma unroll
            for (int ni = 0; ni < 4; ni++) {
                const int col = bm + wn * 32 + ni * 8 + tcol;   // even
                const int gcol = col >> 1;
                const float b0 = bias[col];
                const float b1 = bias[col + 1];
                {
                    const float z1 = acc[mi][ni][0] + b0;
                    const float z3 = acc[mi][ni][1] + b1;
                    const float g = (z1 / (1.f + expf(-z1))) * z3;
                    bf16 hi, lo;
                    split_f32(g, hi, lo);
                    Ghi[r0 * (size_t)ldg + gcol] = hi;
                    Glo[r0 * (size_t)ldg + gcol] = lo;
                }
                {
                    const float z1 = acc[mi][ni][2] + b0;
                    const float z3 = acc[mi][ni][3] + b1;
                    const float g = (z1 / (1.f + expf(-z1))) * z3;
                    bf16 hi, lo;
                    split_f32(g, hi, lo);
                    Ghi[(r0 + 8) * (size_t)ldg + gcol] = hi;
                    Glo[(r0 + 8) * (size_t)ldg + gcol] = lo;
                }
            }
        }
    }
}

// ---------------------------------------------------------------------------
// Tensor-core flash attention v2: 128-query tile, 64-key tiles, fused q/k
// per-head rmsnorm at load, bf16x3 mma, fp32 online softmax.
// 256 threads = 8 warps; warp (wm=wid&3, wn=wid>>2) owns 32x32 output quad.
// ---------------------------------------------------------------------------
#define QT 128
#define ALD 72
#define A_QH 0
#define A_QL (QT * ALD)
#define A_KH (2 * QT * ALD)
#define A_KL (A_KH + 64 * ALD)
#define A_VH (A_KH + 2 * 64 * ALD)
#define A_VL (A_KH + 3 * 64 * ALD)
#define A_PH (A_KH + 4 * 64 * ALD)
#define A_PL (A_PH + QT * ALD)
#define A_BF_TOT (A_PH + 2 * QT * ALD)
#define ATT_SMEM_BYTES (A_BF_TOT * 2 + (QT * 64 + 3 * QT) * 4)   // 144896

__global__ void __launch_bounds__(256)
attn_mma_kernel(const float* __restrict__ q, const float* __restrict__ k,
                const float* __restrict__ v,
                const float* __restrict__ qnw, const float* __restrict__ knw,
                bf16* __restrict__ ohi, bf16* __restrict__ olo,
                const int* __restrict__ winp, int qs)
{
    extern __shared__ __align__(16) char smraw[];
    bf16* sb = (bf16*)smraw;
    float* Ss  = (float*)(smraw + A_BF_TOT * 2);
    float* m_s = Ss + QT * 64;
    float* l_s = m_s + QT;
    float* sc_s = l_s + QT;

    const int q0 = blockIdx.x * QT;
    const int h  = blockIdx.y;
    const int b  = blockIdx.z;
    const int tid = threadIdx.x;
    const int lane = tid & 31;
    const int wid = tid >> 5;
    const int wm = wid & 3;
    const int wn = wid >> 2;
    const int win = *winp;

    const uint32_t sbA = (uint32_t)__cvta_generic_to_shared(sb);

    // Q load + per-head rmsnorm + split (16 lanes per row)
    const size_t base_q = ((size_t)(b * LL + q0)) * qs + h * HD;
    for (int i = tid; i < QT * 16; i += 256) {
        const int r = i >> 4;
        const int c4 = (i & 15) * 4;
        const float4 qv = *(const float4*)&q[base_q + (size_t)r * qs + c4];
        float vv[4] = {qv.x, qv.y, qv.z, qv.w};
#pragma unroll
        for (int j = 0; j < 4; j++) vv[j] = fminf(fmaxf(vv[j], -10000.f), 10000.f);
        float ss = vv[0] * vv[0] + vv[1] * vv[1] + vv[2] * vv[2] + vv[3] * vv[3];
        ss += __shfl_xor_sync(0xffffffffu, ss, 1);
        ss += __shfl_xor_sync(0xffffffffu, ss, 2);
        ss += __shfl_xor_sync(0xffffffffu, ss, 4);
        ss += __shfl_xor_sync(0xffffffffu, ss, 8);
        const float inv = 1.f / sqrtf(fmaxf(ss / 64.f, EPSV) + EPSV);
#pragma unroll
        for (int j = 0; j < 4; j++) {
            float o = vv[j] * inv * qnw[c4 + j];
            if (!isfinite(o)) o = 0.f;
            bf16 hi, lo;
            split_f32(o, hi, lo);
            sb[A_QH + r * ALD + c4 + j] = hi;
            sb[A_QL + r * ALD + c4 + j] = lo;
        }
    }
    if (tid < QT) { m_s[tid] = -INFINITY; l_s[tid] = 0.f; }

    float accO[2][4][4];
#pragma unroll
    for (int mi = 0; mi < 2; mi++)
#pragma unroll
        for (int i = 0; i < 4; i++)
#pragma unroll
            for (int j = 0; j < 4; j++) accO[mi][i][j] = 0.f;

    int lo0 = q0 - win + 1;
    if (lo0 < 0) lo0 = 0;
    const int kt0 = lo0 >> 6;
    const int kt1 = (q0 + QT - 1) >> 6;

    const int a_row_b = wm * 32 + (lane & 15);
    const int a_colsel = ((lane >> 4) & 1) << 3;
    const int b_row0 = wn * 32 + (((lane >> 4) & 1) << 3) + (lane & 7);
    const int b_colsel = ((lane >> 3) & 1) << 3;
    const int trow = lane >> 2;
    const int tcol = (lane & 3) * 2;

    __syncthreads();

    for (int kt = kt0; kt <= kt1; kt++) {
        const int j0 = kt << 6;
        const size_t base_k = ((size_t)(b * LL + j0)) * qs + h * HD;

        // K load + per-head rmsnorm + split; V load transposed + split
        for (int i = tid; i < 64 * 16; i += 256) {
            const int r = i >> 4;
            const int c4 = (i & 15) * 4;
            const float4 kv = *(const float4*)&k[base_k + (size_t)r * qs + c4];
            float kk[4] = {kv.x, kv.y, kv.z, kv.w};
#pragma unroll
            for (int j = 0; j < 4; j++) kk[j] = fminf(fmaxf(kk[j], -10000.f), 10000.f);
            float ss = kk[0] * kk[0] + kk[1] * kk[1] + kk[2] * kk[2] + kk[3] * kk[3];
            ss += __shfl_xor_sync(0xffffffffu, ss, 1);
            ss += __shfl_xor_sync(0xffffffffu, ss, 2);
            ss += __shfl_xor_sync(0xffffffffu, ss, 4);
            ss += __shfl_xor_sync(0xffffffffu, ss, 8);
            const float inv = 1.f / sqrtf(fmaxf(ss / 64.f, EPSV) + EPSV);
            const float4 vvv = *(const float4*)&v[base_k + (size_t)r * qs + c4];
            const float va[4] = {vvv.x, vvv.y, vvv.z, vvv.w};
#pragma unroll
            for (int j = 0; j < 4; j++) {
                float o = kk[j] * inv * knw[c4 + j];
                if (!isfinite(o)) o = 0.f;
                bf16 hi, lo;
                split_f32(o, hi, lo);
                sb[A_KH + r * ALD + c4 + j] = hi;
                sb[A_KL + r * ALD + c4 + j] = lo;
                split_f32(va[j], hi, lo);
                sb[A_VH + (c4 + j) * ALD + r] = hi;
                sb[A_VL + (c4 + j) * ALD + r] = lo;
            }
        }
        __syncthreads();

        // S = Q K^T (bf16x3)
        float accS[2][4][4];
#pragma unroll
        for (int mi = 0; mi < 2; mi++)
#pragma unroll
            for (int i = 0; i < 4; i++)
#pragma unroll
                for (int j = 0; j < 4; j++) accS[mi][i][j] = 0.f;

#pragma unroll
        for (int kk = 0; kk < 4; kk++) {
            uint32_t ah[2][4], al[2][4], bh[4][2], bl[4][2];
#pragma unroll
            for (int mi = 0; mi < 2; mi++) {
                const uint32_t aoff =
                    (uint32_t)((a_row_b + mi * 16) * ALD + kk * 16 + a_colsel) * 2;
                ldm4(ah[mi], sbA + A_QH * 2 + aoff);
                ldm4(al[mi], sbA + A_QL * 2 + aoff);
            }
#pragma unroll
            for (int p = 0; p < 2; p++) {
                const uint32_t boff =
                    (uint32_t)((b_row0 + p * 16) * ALD + kk * 16 + b_colsel) * 2;
                uint32_t th[4], tl[4];
                ldm4(th, sbA + A_KH * 2 + boff);
                ldm4(tl, sbA + A_KL * 2 + boff);
                bh[p * 2][0] = th[0]; bh[p * 2][1] = th[1];
                bh[p * 2 + 1][0] = th[2]; bh[p * 2 + 1][1] = th[3];
                bl[p * 2][0] = tl[0]; bl[p * 2][1] = tl[1];
                bl[p * 2 + 1][0] = tl[2]; bl[p * 2 + 1][1] = tl[3];
            }
#pragma unroll
            for (int mi = 0; mi < 2; mi++)
#pragma unroll
                for (int nt = 0; nt < 4; nt++) {
                    mma16816(accS[mi][nt], ah[mi], bh[nt]);
                    mma16816(accS[mi][nt], ah[mi], bl[nt]);
                    mma16816(accS[mi][nt], al[mi], bh[nt]);
                }
        }

        // masked scaled S -> Ss
#pragma unroll
        for (int mi = 0; mi < 2; mi++) {
            const int rr1 = wm * 32 + mi * 16 + trow;
            const int qi1 = q0 + rr1;
            const int qi2 = qi1 + 8;
#pragma unroll
            for (int nt = 0; nt < 4; nt++) {
                const int c = wn * 32 + nt * 8 + tcol;
                const int ja = j0 + c, jb = ja + 1;
                bool ok;
                ok = (ja <= qi1) && (qi1 - ja < win);
                Ss[rr1 * 64 + c]           = ok ? accS[mi][nt][0] * 0.125f : -INFINITY;
                ok = (jb <= qi1) && (qi1 - jb < win);
                Ss[rr1 * 64 + c + 1]       = ok ? accS[mi][nt][1] * 0.125f : -INFINITY;
                ok = (ja <= qi2) && (qi2 - ja < win);
                Ss[(rr1 + 8) * 64 + c]     = ok ? accS[mi][nt][2] * 0.125f : -INFINITY;
                ok = (jb <= qi2) && (qi2 - jb < win);
                Ss[(rr1 + 8) * 64 + c + 1] = ok ? accS[mi][nt][3] * 0.125f : -INFINITY;
            }
        }
        __syncthreads();

        // online softmax: 2 threads per row, 32 cols each
        {
            const int row = tid >> 1;
            const int part = tid & 1;
            float* srow = &Ss[row * 64 + part * 32];
            float tm = -INFINITY;
#pragma unroll
            for (int c = 0; c < 32; c++) tm = fmaxf(tm, srow[c]);
            tm = fmaxf(tm, __shfl_xor_sync(0xffffffffu, tm, 1));

            const float mold = m_s[row];
            const float nm = fmaxf(mold, tm);
            float scale;
            float psum = 0.f;
            if (nm == -INFINITY) {
                scale = 1.f;
#pragma unroll
                for (int c = 0; c < 32; c++) srow[c] = 0.f;
            } else {
                scale = expf(mold - nm);
#pragma unroll
                for (int c = 0; c < 32; c++) {
                    const float p = expf(srow[c] - nm);
                    srow[c] = p;
                    psum += p;
                }
            }
            psum += __shfl_xor_sync(0xffffffffu, psum, 1);
            if (part == 0) {
                m_s[row] = nm;
                l_s[row] = l_s[row] * scale + psum;
                sc_s[row] = scale;
            }
        }
        __syncthreads();

        // rescale accO; convert P -> bf16 hi/lo
#pragma unroll
        for (int mi = 0; mi < 2; mi++) {
            const int rr1 = wm * 32 + mi * 16 + trow;
            const float s1 = sc_s[rr1];
            const float s2 = sc_s[rr1 + 8];
#pragma unroll
            for (int nt = 0; nt < 4; nt++) {
                accO[mi][nt][0] *= s1; accO[mi][nt][1] *= s1;
                accO[mi][nt][2] *= s2; accO[mi][nt][3] *= s2;
            }
        }
        for (int i = tid; i < QT * 16; i += 256) {
            const int r = i >> 4;
            const int c4 = (i & 15) * 4;
            const float4 pv = *(const float4*)&Ss[r * 64 + c4];
            const float pa[4] = {pv.x, pv.y, pv.z, pv.w};
#pragma unroll
            for (int j = 0; j < 4; j++) {
                bf16 hi, lo;
                split_f32(pa[j], hi, lo);
                sb[A_PH + r * ALD + c4 + j] = hi;
                sb[A_PL + r * ALD + c4 + j] = lo;
            }
        }
        __syncthreads();

        // O += P V (bf16x3)
#pragma unroll
        for (int kk = 0; kk < 4; kk++) {
            uint32_t ah[2][4], al[2][4], bh[4][2], bl[4][2];
#pragma unroll
            for (int mi = 0; mi < 2; mi++) {
                const uint32_t aoff =
                    (uint32_t)((a_row_b + mi * 16) * ALD + kk * 16 + a_colsel) * 2;
                ldm4(ah[mi], sbA + A_PH * 2 + aoff);
                ldm4(al[mi], sbA + A_PL * 2 + aoff);
            }
#pragma unroll
            for (int p = 0; p < 2; p++) {
                const uint32_t boff =
                    (uint32_t)((b_row0 + p * 16) * ALD + kk * 16 + b_colsel) * 2;
                uint32_t th[4], tl[4];
                ldm4(th, sbA + A_VH * 2 + boff);
                ldm4(tl, sbA + A_VL * 2 + boff);
                bh[p * 2][0] = th[0]; bh[p * 2][1] = th[1];
                bh[p * 2 + 1][0] = th[2]; bh[p * 2 + 1][1] = th[3];
                bl[p * 2][0] = tl[0]; bl[p * 2][1] = tl[1];
                bl[p * 2 + 1][0] = tl[2]; bl[p * 2 + 1][1] = tl[3];
            }
#pragma unroll
            for (int mi = 0; mi < 2; mi++)
#pragma unroll
                for (int nt = 0; nt < 4; nt++) {
                    mma16816(accO[mi][nt], ah[mi], bh[nt]);
                    mma16816(accO[mi][nt], ah[mi], bl[nt]);
                    mma16816(accO[mi][nt], al[mi], bh[nt]);
                }
        }
        __syncthreads();
    }

    // epilogue
#pragma unroll
    for (int mi = 0; mi < 2; mi++) {
        const int rr1 = wm * 32 + mi * 16 + trow;
        const float li1 = 1.f / l_s[rr1];
        const float li2 = 1.f / l_s[rr1 + 8];
        const size_t o1 = ((size_t)(b * LL + q0 + rr1)) * DD + h * HD;
        const size_t o2 = o1 + (size_t)8 * DD;
#pragma unroll
        for (int nt = 0; nt < 4; nt++) {
            const int c = wn * 32 + nt * 8 + tcol;
            float vals[4] = {accO[mi][nt][0] * li1, accO[mi][nt][1] * li1,
                             accO[mi][nt][2] * li2, accO[mi][nt][3] * li2};
#pragma unroll
            for (int j = 0; j < 4; j++) if (!isfinite(vals[j])) vals[j] = 0.f;
            bf16 hi, lo;
            split_f32(vals[0], hi, lo); ohi[o1 + c] = hi;     olo[o1 + c] = lo;
            split_f32(vals[1], hi, lo); ohi[o1 + c + 1] = hi; olo[o1 + c + 1] = lo;
            split_f32(vals[2], hi, lo); ohi[o2 + c] = hi;     olo[o2 + c] = lo;
            split_f32(vals[3], hi, lo); ohi[o2 + c + 1] = hi; olo[o2 + c + 1] = lo;
        }
    }
}

// ---------------------------------------------------------------------------
// Launch
// ---------------------------------------------------------------------------
extern "C" void kernel_launch(void* const* d_in, const int* in_sizes, int n_in,
                              void* d_out, int out_size)
{
    const float* x    = (const float*)d_in[0];
    const float* wq_w = (const float*)d_in[1];
    const float* wq_b = (const float*)d_in[2];
    const float* wk_w = (const float*)d_in[3];
    const float* wk_b = (const float*)d_in[4];
    const float* wv_w = (const float*)d_in[5];
    const float* wv_b = (const float*)d_in[6];
    const float* wo_w = (const float*)d_in[7];
    const float* wo_b = (const float*)d_in[8];
    const float* q_nw = (const float*)d_in[9];
    const float* k_nw = (const float*)d_in[10];
    const float* s_nw = (const float*)d_in[11];
    const float* sp_nw= (const float*)d_in[12];
    const float* f_nw = (const float*)d_in[13];
    const float* fp_nw= (const float*)d_in[14];
    const float* w1_w = (const float*)d_in[15];
    const float* w1_b = (const float*)d_in[16];
    const float* w2_w = (const float*)d_in[17];
    const float* w2_b = (const float*)d_in[18];
    const float* w3_w = (const float*)d_in[19];
    const float* w3_b = (const float*)d_in[20];
    const int*   winp = (const int*)d_in[21];

    float* fbase = nullptr;
    cudaGetSymbolAddress((void**)&fbase, g_scratch);
    float* qkv = fbase;                       // [4096][3072]
    float* a   = fbase + 3 * SZ_D;
    float* h   = fbase + 4 * SZ_D;
    float* f   = fbase + 5 * SZ_D;

    float* bqkv = nullptr;
    cudaGetSymbolAddress((void**)&bqkv, g_bias_qkv);
    float* bffn = nullptr;
    cudaGetSymbolAddress((void**)&bffn, g_bias_ffn);

    bf16* bbase = nullptr;
    cudaGetSymbolAddress((void**)&bbase, g_bscratch);
    bf16* xn_h = bbase + 0 * BSZ_ACT;
    bf16* xn_l = bbase + 1 * BSZ_ACT;
    bf16* at_h = bbase + 2 * BSZ_ACT;
    bf16* at_l = bbase + 3 * BSZ_ACT;
    bf16* hn_h = bbase + 4 * BSZ_ACT;
    bf16* hn_l = bbase + 5 * BSZ_ACT;
    bf16* g_h  = bbase + 6 * BSZ_ACT;
    bf16* g_l  = bbase + 6 * BSZ_ACT + BSZ_G;
    bf16* w_h  = bbase + 6 * BSZ_ACT + 2 * BSZ_G;
    bf16* w_l  = bbase + 6 * BSZ_ACT + 2 * BSZ_G + BSZ_W;

    float* out = (float*)d_out;

    cudaFuncSetAttribute(gemm_bf16x3,
                         cudaFuncAttributeMaxDynamicSharedMemorySize, GEMM_SMEM);
    cudaFuncSetAttribute(attn_mma_kernel,
                         cudaFuncAttributeMaxDynamicSharedMemorySize,
                         ATT_SMEM_BYTES);

    // biases for fused GEMMs
    bias_concat_k<<<(I2P + 255) / 256, 256>>>(wq_b, wk_b, wv_b, w1_b, w3_b,
                                              bqkv, bffn);

    // 1) xn = rmsnorm(x, seq_norm_w) -> bf16 split
    rmsnorm_split_k<DD, 256><<<NROWS, 256>>>(x, s_nw, xn_h, xn_l);

    // 2) fused QKV projection
    {
        const size_t wN8 = (size_t)DD * DD / 8;
        conv_split8_k<<<(int)((wN8 + 255) / 256), 256>>>(wq_w, w_h, w_l, DD, DD, DD, DD);
        conv_split8_k<<<(int)((wN8 + 255) / 256), 256>>>(wk_w, w_h + (size_t)1024 * 1024,
                                                         w_l + (size_t)1024 * 1024, DD, DD, DD, DD);
        conv_split8_k<<<(int)((wN8 + 255) / 256), 256>>>(wv_w, w_h + (size_t)2048 * 1024,
                                                         w_l + (size_t)2048 * 1024, DD, DD, DD, DD);
        dim3 grid(QKVD / 128, NROWS / 128);
        gemm_bf16x3<<<grid, 256, GEMM_SMEM>>>(xn_h, xn_l, w_h, w_l, bqkv, qkv,
                                              QKVD, DD, QKVD, 0, nullptr, nullptr, 0);
    }

    // 3) tensor-core attention (q/k rmsnorm fused) -> bf16 split output
    {
        dim3 grid(LL / QT, HH, BB);
        attn_mma_kernel<<<grid, 256, ATT_SMEM_BYTES>>>(qkv, qkv + 1024, qkv + 2048,
                                                       q_nw, k_nw,
                                                       at_h, at_l, winp, QKVD);
    }

    // 4) output projection
    {
        const size_t wN8 = (size_t)DD * DD / 8;
        conv_split8_k<<<(int)((wN8 + 255) / 256), 256>>>(wo_w, w_h, w_l, DD, DD, DD, DD);
        dim3 grid(DD / 128, NROWS / 128);
        gemm_bf16x3<<<grid, 256, GEMM_SMEM>>>(at_h, at_l, w_h, w_l, wo_b, a,
                                              DD, DD, DD, 0, nullptr, nullptr, 0);
    }

    // 5) h = x + rmsnorm(a, seq_post_norm_w)
    rmsnorm_k<DD, 256><<<NROWS, 256>>>(a, sp_nw, x, h);

    // 6) hn = rmsnorm(h, ffn_norm_w) -> bf16 split
    rmsnorm_split_k<DD, 256><<<NROWS, 256>>>(h, f_nw, hn_h, hn_l);

    // 7) fused interleaved w1/w3 GEMM with silu epilogue -> g (bf16 split)
    {
        const size_t wN8 = (size_t)I2P * DD / 8;
        conv_split_ilv8_k<<<(int)((wN8 + 255) / 256), 256>>>(w1_w, w3_w, w_h, w_l);
        dim3 grid(I2P / 128, NROWS / 128);
        gemm_bf16x3<<<grid, 256, GEMM_SMEM>>>(hn_h, hn_l, w_h, w_l, bffn, nullptr,
                                              I2P, DD, 0, 1, g_h, g_l, IKP);
    }

    // 8) f = g @ w2^T + b2  (K = IKP, weight K-padded)
    {
        const size_t wN8 = (size_t)DD * IKP / 8;
        conv_split8_k<<<(int)((wN8 + 255) / 256), 256>>>(w2_w, w_h, w_l,
                                                         DD, II, DD, IKP);
        dim3 grid(DD / 128, NROWS / 128);
        gemm_bf16x3<<<grid, 256, GEMM_SMEM>>>(g_h, g_l, w_h, w_l, w2_b, f,
                                              DD, IKP, DD, 0, nullptr, nullptr, 0);
    }

    // 9) out = h + rmsnorm(f, ffn_post_norm_w)
    rmsnorm_k<DD, 256><<<NROWS, 256>>>(f, fp_nw, h, out);
}

// round 14
// speedup vs baseline: 1.0086x; 1.0086x over previous
#include <cuda_runtime.h>
#include <cuda_bf16.h>
#include <math.h>
#include <stdint.h>

typedef __nv_bfloat16 bf16;

// ---------------------------------------------------------------------------
// Problem constants
// ---------------------------------------------------------------------------
#define BB 4
#define LL 1024
#define DD 1024
#define HH 16
#define HD 64
#define II 3280
#define I2 6560
#define I2P 6656               // I2 padded to 128
#define IKP 3328               // II padded to 128 (w2 K / g stride)
#define QKVD 3072
#define NROWS (BB * LL)        // 4096
#define EPSV 1e-5f

#define SZ_D ((size_t)NROWS * DD)

// fp32 scratch: qkv(3*SZ_D), a, h, f
__device__ float g_scratch[6 * SZ_D];
__device__ float g_bias_qkv[QKVD];
__device__ float g_bias_ffn[I2P];

// bf16 scratch (hi/lo pairs)
#define BSZ_ACT ((size_t)NROWS * DD)
#define BSZ_G   ((size_t)NROWS * IKP)
#define BSZ_W   ((size_t)I2P * 1024)
__device__ bf16 g_bscratch[6 * BSZ_ACT + 2 * BSZ_G + 2 * BSZ_W];

// ---------------------------------------------------------------------------
// helpers
// ---------------------------------------------------------------------------
__device__ __forceinline__ void split_f32(float v, bf16& hi, bf16& lo) {
    hi = __float2bfloat16(v);
    lo = __float2bfloat16(v - __bfloat162float(hi));
}

__device__ __forceinline__ void cpa16p(bf16* dst, const bf16* src, bool valid) {
    uint32_t d = (uint32_t)__cvta_generic_to_shared(dst);
    int sz = valid ? 16 : 0;
    asm volatile("cp.async.ca.shared.global [%0], [%1], 16, %2;\n"
                 :: "r"(d), "l"(src), "r"(sz));
}
__device__ __forceinline__ void cpa_commit() {
    asm volatile("cp.async.commit_group;\n" ::: "memory");
}
__device__ __forceinline__ void cpa_wait_all() {
    asm volatile("cp.async.wait_group 0;\n" ::: "memory");
}

__device__ __forceinline__ void ldm4(uint32_t* r, uint32_t addr) {
    asm volatile("ldmatrix.sync.aligned.m8n8.x4.shared.b16 {%0,%1,%2,%3}, [%4];\n"
                 : "=r"(r[0]), "=r"(r[1]), "=r"(r[2]), "=r"(r[3]) : "r"(addr));
}

__device__ __forceinline__ void mma16816(float* d, const uint32_t* a, const uint32_t* b) {
    asm volatile(
        "mma.sync.aligned.m16n8k16.row.col.f32.bf16.bf16.f32 "
        "{%0,%1,%2,%3}, {%4,%5,%6,%7}, {%8,%9}, {%0,%1,%2,%3};\n"
        : "+f"(d[0]), "+f"(d[1]), "+f"(d[2]), "+f"(d[3])
        : "r"(a[0]), "r"(a[1]), "r"(a[2]), "r"(a[3]), "r"(b[0]), "r"(b[1]));
}

__device__ __forceinline__ void store_split8(bf16* hi, bf16* lo, const float* v) {
    bf16 hbuf[8], lbuf[8];
#pragma unroll
    for (int i = 0; i < 8; i++) split_f32(v[i], hbuf[i], lbuf[i]);
    *(uint4*)hi = *(const uint4*)hbuf;
    *(uint4*)lo = *(const uint4*)lbuf;
}

// ---------------------------------------------------------------------------
// RMSNorm (fp32 out, optional residual)
// ---------------------------------------------------------------------------
template <int W, int T>
__global__ void rmsnorm_k(const float* __restrict__ in,
                          const float* __restrict__ w,
                          const float* __restrict__ resid,
                          float* __restrict__ out)
{
    constexpr int PER = W / T;
    const size_t row = blockIdx.x;
    const float* xr = in + row * (size_t)W;
    float vals[PER];
    float ss = 0.f;
#pragma unroll
    for (int i = 0; i < PER; i++) {
        float vv = xr[threadIdx.x + i * T];
        vv = fminf(fmaxf(vv, -10000.f), 10000.f);
        vals[i] = vv;
        ss += vv * vv;
    }
    __shared__ float red[T];
    red[threadIdx.x] = ss;
    __syncthreads();
#pragma unroll
    for (int s = T / 2; s > 0; s >>= 1) {
        if (threadIdx.x < s) red[threadIdx.x] += red[threadIdx.x + s];
        __syncthreads();
    }
    const float mean = red[0] / (float)W;
    const float inv = 1.f / sqrtf(fmaxf(mean, EPSV) + EPSV);
#pragma unroll
    for (int i = 0; i < PER; i++) {
        const int c = threadIdx.x + i * T;
        float o = vals[i] * inv * w[c];
        if (!isfinite(o)) o = 0.f;
        if (resid) o += resid[row * (size_t)W + c];
        out[row * (size_t)W + c] = o;
    }
}

// RMSNorm writing bf16 hi/lo split
template <int W, int T>
__global__ void rmsnorm_split_k(const float* __restrict__ in,
                                const float* __restrict__ w,
                                bf16* __restrict__ ohi,
                                bf16* __restrict__ olo)
{
    constexpr int PER = W / T;
    const size_t row = blockIdx.x;
    const float* xr = in + row * (size_t)W;
    float vals[PER];
    float ss = 0.f;
#pragma unroll
    for (int i = 0; i < PER; i++) {
        float vv = xr[threadIdx.x + i * T];
        vv = fminf(fmaxf(vv, -10000.f), 10000.f);
        vals[i] = vv;
        ss += vv * vv;
    }
    __shared__ float red[T];
    red[threadIdx.x] = ss;
    __syncthreads();
#pragma unroll
    for (int s = T / 2; s > 0; s >>= 1) {
        if (threadIdx.x < s) red[threadIdx.x] += red[threadIdx.x + s];
        __syncthreads();
    }
    const float mean = red[0] / (float)W;
    const float inv = 1.f / sqrtf(fmaxf(mean, EPSV) + EPSV);
#pragma unroll
    for (int i = 0; i < PER; i++) {
        const int c = threadIdx.x + i * T;
        float o = vals[i] * inv * w[c];
        if (!isfinite(o)) o = 0.f;
        bf16 hi, lo;
        split_f32(o, hi, lo);
        ohi[row * (size_t)W + c] = hi;
        olo[row * (size_t)W + c] = lo;
    }
}

// ---------------------------------------------------------------------------
// Vectorized weight split (8 elems/thread)
// ---------------------------------------------------------------------------
__global__ void conv_split8_k(const float* __restrict__ src,
                              bf16* __restrict__ hi, bf16* __restrict__ lo,
                              int rows, int K0, int rowsPad, int KP)
{
    size_t i8 = ((size_t)blockIdx.x * blockDim.x + threadIdx.x) * 8;
    size_t n = (size_t)rowsPad * KP;
    if (i8 >= n) return;
    int r = (int)(i8 / KP);
    int c = (int)(i8 % KP);
    float v[8];
    if (r < rows && c + 8 <= K0) {
        const float* s = src + (size_t)r * K0 + c;
        *(float4*)&v[0] = *(const float4*)s;
        *(float4*)&v[4] = *(const float4*)(s + 4);
    } else {
#pragma unroll
        for (int i = 0; i < 8; i++) {
            int cc = c + i;
            v[i] = (r < rows && cc < K0) ? src[(size_t)r * K0 + cc] : 0.f;
        }
    }
    store_split8(hi + i8, lo + i8, v);
}

// Interleaved w1/w3 split
__global__ void conv_split_ilv8_k(const float* __restrict__ w1,
                                  const float* __restrict__ w3,
                                  bf16* __restrict__ hi, bf16* __restrict__ lo)
{
    size_t i8 = ((size_t)blockIdx.x * blockDim.x + threadIdx.x) * 8;
    size_t n = (size_t)I2P * DD;
    if (i8 >= n) return;
    int r = (int)(i8 / DD);
    int c = (int)(i8 % DD);
    int sr = r >> 1;
    float v[8];
    if (sr < II) {
        const float* s = ((r & 1) ? w3 : w1) + (size_t)sr * DD + c;
        *(float4*)&v[0] = *(const float4*)s;
        *(float4*)&v[4] = *(const float4*)(s + 4);
    } else {
#pragma unroll
        for (int i = 0; i < 8; i++) v[i] = 0.f;
    }
    store_split8(hi + i8, lo + i8, v);
}

// bias concat
__global__ void bias_concat_k(const float* qb, const float* kb, const float* vb,
                              const float* b1, const float* b3,
                              float* outQKV, float* outFFN)
{
    int i = blockIdx.x * blockDim.x + threadIdx.x;
    if (i < 1024) {
        outQKV[i] = qb[i];
        outQKV[1024 + i] = kb[i];
        outQKV[2048 + i] = vb[i];
    }
    if (i < I2P) {
        int sr = i >> 1;
        outFFN[i] = (sr < II) ? ((i & 1) ? b3[sr] : b1[sr]) : 0.f;
    }
}

// ---------------------------------------------------------------------------
// bf16x3 tensor-core GEMM (NT) — R9 config + forced 2 CTAs/SM.
// CTA 128x128, BK=32, 256 threads (8 warps 2x4, 64x32/warp), SKT=40.
// fuse_silu: interleaved (z1,z3) cols -> g=silu(z1)*z3 bf16 hi/lo split out.
// ---------------------------------------------------------------------------
#define SKT 40
#define STAGE_ELEMS (128 * SKT)
#define GEMM_SMEM (2 * 4 * STAGE_ELEMS * 2)        // 81920 bytes

__global__ void __launch_bounds__(256, 2)
gemm_bf16x3(const bf16* __restrict__ Ah, const bf16* __restrict__ Al,
            const bf16* __restrict__ Bh, const bf16* __restrict__ Bl,
            const float* __restrict__ bias, float* __restrict__ C,
            int Mtot, int K, int ldc,
            int fuse_silu, bf16* __restrict__ Ghi, bf16* __restrict__ Glo,
            int ldg)
{
    extern __shared__ __align__(16) bf16 smem[];

    const int tid = threadIdx.x;
    const int lane = tid & 31;
    const int wid = tid >> 5;
    const int wm = wid & 1;
    const int wn = wid >> 1;

    const int bm = blockIdx.x * 128;
    const int bn = blockIdx.y * 128;

    const int ldr = tid >> 1;
    const int ldcol = (tid & 1) * 16;

    const bf16* gAh = Ah + (size_t)(bn + ldr) * K + ldcol;
    const bf16* gAl = Al + (size_t)(bn + ldr) * K + ldcol;
    const bool bvalid = (bm + ldr) < Mtot;
    const bf16* gBh = Bh + (size_t)(bm + ldr) * K + ldcol;
    const bf16* gBl = Bl + (size_t)(bm + ldr) * K + ldcol;

    const int s_off = ldr * SKT + ldcol;

    float acc[4][4][4];
#pragma unroll
    for (int i = 0; i < 4; i++)
#pragma unroll
        for (int j = 0; j < 4; j++)
#pragma unroll
            for (int r = 0; r < 4; r++) acc[i][j][r] = 0.f;

    const int nk = K >> 5;

    {
        bf16* s = smem;
        cpa16p(s + 0 * STAGE_ELEMS + s_off,     gAh,     true);
        cpa16p(s + 0 * STAGE_ELEMS + s_off + 8, gAh + 8, true);
        cpa16p(s + 1 * STAGE_ELEMS + s_off,     gAl,     true);
        cpa16p(s + 1 * STAGE_ELEMS + s_off + 8, gAl + 8, true);
        cpa16p(s + 2 * STAGE_ELEMS + s_off,     gBh,     bvalid);
        cpa16p(s + 2 * STAGE_ELEMS + s_off + 8, gBh + 8, bvalid);
        cpa16p(s + 3 * STAGE_ELEMS + s_off,     gBl,     bvalid);
        cpa16p(s + 3 * STAGE_ELEMS + s_off + 8, gBl + 8, bvalid);
    }
    cpa_commit();

    const int a_row = wm * 64 + (lane & 15);
    const int a_colsel = ((lane >> 4) & 1) << 3;
    const int b_row0 = wn * 32 + (((lane >> 4) & 1) << 3) + (lane & 7);
    const int b_colsel = ((lane >> 3) & 1) << 3;

    for (int kt = 0; kt < nk; kt++) {
        cpa_wait_all();
        __syncthreads();

        if (kt + 1 < nk) {
            bf16* s = smem + ((kt + 1) & 1) * (4 * STAGE_ELEMS);
            const int ko = (kt + 1) << 5;
            cpa16p(s + 0 * STAGE_ELEMS + s_off,     gAh + ko,     true);
            cpa16p(s + 0 * STAGE_ELEMS + s_off + 8, gAh + ko + 8, true);
            cpa16p(s + 1 * STAGE_ELEMS + s_off,     gAl + ko,     true);
            cpa16p(s + 1 * STAGE_ELEMS + s_off + 8, gAl + ko + 8, true);
            cpa16p(s + 2 * STAGE_ELEMS + s_off,     gBh + ko,     bvalid);
            cpa16p(s + 2 * STAGE_ELEMS + s_off + 8, gBh + ko + 8, bvalid);
            cpa16p(s + 3 * STAGE_ELEMS + s_off,     gBl + ko,     bvalid);
            cpa16p(s + 3 * STAGE_ELEMS + s_off + 8, gBl + ko + 8, bvalid);
        }
        cpa_commit();

        bf16* st = smem + (kt & 1) * (4 * STAGE_ELEMS);
        const uint32_t sAh = (uint32_t)__cvta_generic_to_shared(st + 0 * STAGE_ELEMS);
        const uint32_t sAl = (uint32_t)__cvta_generic_to_shared(st + 1 * STAGE_ELEMS);
        const uint32_t sBh = (uint32_t)__cvta_generic_to_shared(st + 2 * STAGE_ELEMS);
        const uint32_t sBl = (uint32_t)__cvta_generic_to_shared(st + 3 * STAGE_ELEMS);

#pragma unroll
        for (int ks = 0; ks < 2; ks++) {
            const int koff = ks * 16;
            uint32_t ah[4][4], al[4][4], bh[4][2], bl[4][2];
#pragma unroll
            for (int mi = 0; mi < 4; mi++) {
                const uint32_t off =
                    ((a_row + mi * 16) * SKT + koff + a_colsel) * 2;
                ldm4(ah[mi], sAh + off);
                ldm4(al[mi], sAl + off);
            }
#pragma unroll
            for (int p = 0; p < 2; p++) {
                const uint32_t off =
                    ((b_row0 + p * 16) * SKT + koff + b_colsel) * 2;
                uint32_t th[4], tl[4];
                ldm4(th, sBh + off);
                ldm4(tl, sBl + off);
                bh[p * 2][0] = th[0]; bh[p * 2][1] = th[1];
                bh[p * 2 + 1][0] = th[2]; bh[p * 2 + 1][1] = th[3];
                bl[p * 2][0] = tl[0]; bl[p * 2][1] = tl[1];
                bl[p * 2 + 1][0] = tl[2]; bl[p * 2 + 1][1] = tl[3];
            }
#pragma unroll
            for (int mi = 0; mi < 4; mi++)
#pragma unroll
                for (int ni = 0; ni < 4; ni++) {
                    mma16816(acc[mi][ni], ah[mi], bh[ni]);
                    mma16816(acc[mi][ni], ah[mi], bl[ni]);
                    mma16816(acc[mi][ni], al[mi], bh[ni]);
                }
        }
        __syncthreads();
    }

    const int trow = lane >> 2;
    const int tcol = (lane & 3) * 2;
    if (!fuse_silu) {
#pragma unroll
        for (int mi = 0; mi < 4; mi++) {
            const size_t r0 = (size_t)bn + wm * 64 + mi * 16 + trow;
#pragma unroll
            for (int ni = 0; ni < 4; ni++) {
                const int col = bm + wn * 32 + ni * 8 + tcol;
                if (col < Mtot) {
                    const float b0 = bias[col];
                    const float b1 = bias[col + 1];
                    float2 v0 = make_float2(acc[mi][ni][0] + b0, acc[mi][ni][1] + b1);
                    float2 v1 = make_float2(acc[mi][ni][2] + b0, acc[mi][ni][3] + b1);
                    *(float2*)&C[r0 * (size_t)ldc + col] = v0;
                    *(float2*)&C[(r0 + 8) * (size_t)ldc + col] = v1;
                }
            }
        }
    } else {
#pragma unroll
        for (int mi = 0; mi < 4; mi++) {
            const size_t r0 = (size_t)bn + wm * 64 + mi * 16 + trow;
#pragma unroll
            for (int ni = 0; ni < 4; ni++) {
                const int col = bm + wn * 32 + ni * 8 + tcol;   // even
                const int gcol = col >> 1;
                const float b0 = bias[col];
                const float b1 = bias[col + 1];
                {
                    const float z1 = acc[mi][ni][0] + b0;
                    const float z3 = acc[mi][ni][1] + b1;
                    const float g = (z1 / (1.f + expf(-z1))) * z3;
                    bf16 hi, lo;
                    split_f32(g, hi, lo);
                    Ghi[r0 * (size_t)ldg + gcol] = hi;
                    Glo[r0 * (size_t)ldg + gcol] = lo;
                }
                {
                    const float z1 = acc[mi][ni][2] + b0;
                    const float z3 = acc[mi][ni][3] + b1;
                    const float g = (z1 / (1.f + expf(-z1))) * z3;
                    bf16 hi, lo;
                    split_f32(g, hi, lo);
                    Ghi[(r0 + 8) * (size_t)ldg + gcol] = hi;
                    Glo[(r0 + 8) * (size_t)ldg + gcol] = lo;
                }
            }
        }
    }
}

// ---------------------------------------------------------------------------
// Tensor-core flash attention v2 (unchanged from R13): 128-query tile,
// fused q/k rmsnorm, bf16x3 mma, fp32 online softmax.
// ---------------------------------------------------------------------------
#define QT 128
#define ALD 72
#define A_QH 0
#define A_QL (QT * ALD)
#define A_KH (2 * QT * ALD)
#define A_KL (A_KH + 64 * ALD)
#define A_VH (A_KH + 2 * 64 * ALD)
#define A_VL (A_KH + 3 * 64 * ALD)
#define A_PH (A_KH + 4 * 64 * ALD)
#define A_PL (A_PH + QT * ALD)
#define A_BF_TOT (A_PH + 2 * QT * ALD)
#define ATT_SMEM_BYTES (A_BF_TOT * 2 + (QT * 64 + 3 * QT) * 4)

__global__ void __launch_bounds__(256)
attn_mma_kernel(const float* __restrict__ q, const float* __restrict__ k,
                const float* __restrict__ v,
                const float* __restrict__ qnw, const float* __restrict__ knw,
                bf16* __restrict__ ohi, bf16* __restrict__ olo,
                const int* __restrict__ winp, int qs)
{
    extern __shared__ __align__(16) char smraw[];
    bf16* sb = (bf16*)smraw;
    float* Ss  = (float*)(smraw + A_BF_TOT * 2);
    float* m_s = Ss + QT * 64;
    float* l_s = m_s + QT;
    float* sc_s = l_s + QT;

    const int q0 = blockIdx.x * QT;
    const int h  = blockIdx.y;
    const int b  = blockIdx.z;
    const int tid = threadIdx.x;
    const int lane = tid & 31;
    const int wid = tid >> 5;
    const int wm = wid & 3;
    const int wn = wid >> 2;
    const int win = *winp;

    const uint32_t sbA = (uint32_t)__cvta_generic_to_shared(sb);

    const size_t base_q = ((size_t)(b * LL + q0)) * qs + h * HD;
    for (int i = tid; i < QT * 16; i += 256) {
        const int r = i >> 4;
        const int c4 = (i & 15) * 4;
        const float4 qv = *(const float4*)&q[base_q + (size_t)r * qs + c4];
        float vv[4] = {qv.x, qv.y, qv.z, qv.w};
#pragma unroll
        for (int j = 0; j < 4; j++) vv[j] = fminf(fmaxf(vv[j], -10000.f), 10000.f);
        float ss = vv[0] * vv[0] + vv[1] * vv[1] + vv[2] * vv[2] + vv[3] * vv[3];
        ss += __shfl_xor_sync(0xffffffffu, ss, 1);
        ss += __shfl_xor_sync(0xffffffffu, ss, 2);
        ss += __shfl_xor_sync(0xffffffffu, ss, 4);
        ss += __shfl_xor_sync(0xffffffffu, ss, 8);
        const float inv = 1.f / sqrtf(fmaxf(ss / 64.f, EPSV) + EPSV);
#pragma unroll
        for (int j = 0; j < 4; j++) {
            float o = vv[j] * inv * qnw[c4 + j];
            if (!isfinite(o)) o = 0.f;
            bf16 hi, lo;
            split_f32(o, hi, lo);
            sb[A_QH + r * ALD + c4 + j] = hi;
            sb[A_QL + r * ALD + c4 + j] = lo;
        }
    }
    if (tid < QT) { m_s[tid] = -INFINITY; l_s[tid] = 0.f; }

    float accO[2][4][4];
#pragma unroll
    for (int mi = 0; mi < 2; mi++)
#pragma unroll
        for (int i = 0; i < 4; i++)
#pragma unroll
            for (int j = 0; j < 4; j++) accO[mi][i][j] = 0.f;

    int lo0 = q0 - win + 1;
    if (lo0 < 0) lo0 = 0;
    const int kt0 = lo0 >> 6;
    const int kt1 = (q0 + QT - 1) >> 6;

    const int a_row_b = wm * 32 + (lane & 15);
    const int a_colsel = ((lane >> 4) & 1) << 3;
    const int b_row0 = wn * 32 + (((lane >> 4) & 1) << 3) + (lane & 7);
    const int b_colsel = ((lane >> 3) & 1) << 3;
    const int trow = lane >> 2;
    const int tcol = (lane & 3) * 2;

    __syncthreads();

    for (int kt = kt0; kt <= kt1; kt++) {
        const int j0 = kt << 6;
        const size_t base_k = ((size_t)(b * LL + j0)) * qs + h * HD;

        for (int i = tid; i < 64 * 16; i += 256) {
            const int r = i >> 4;
            const int c4 = (i & 15) * 4;
            const float4 kv = *(const float4*)&k[base_k + (size_t)r * qs + c4];
            float kk[4] = {kv.x, kv.y, kv.z, kv.w};
#pragma unroll
            for (int j = 0; j < 4; j++) kk[j] = fminf(fmaxf(kk[j], -10000.f), 10000.f);
            float ss = kk[0] * kk[0] + kk[1] * kk[1] + kk[2] * kk[2] + kk[3] * kk[3];
            ss += __shfl_xor_sync(0xffffffffu, ss, 1);
            ss += __shfl_xor_sync(0xffffffffu, ss, 2);
            ss += __shfl_xor_sync(0xffffffffu, ss, 4);
            ss += __shfl_xor_sync(0xffffffffu, ss, 8);
            const float inv = 1.f / sqrtf(fmaxf(ss / 64.f, EPSV) + EPSV);
            const float4 vvv = *(const float4*)&v[base_k + (size_t)r * qs + c4];
            const float va[4] = {vvv.x, vvv.y, vvv.z, vvv.w};
#pragma unroll
            for (int j = 0; j < 4; j++) {
                float o = kk[j] * inv * knw[c4 + j];
                if (!isfinite(o)) o = 0.f;
                bf16 hi, lo;
                split_f32(o, hi, lo);
                sb[A_KH + r * ALD + c4 + j] = hi;
                sb[A_KL + r * ALD + c4 + j] = lo;
                split_f32(va[j], hi, lo);
                sb[A_VH + (c4 + j) * ALD + r] = hi;
                sb[A_VL + (c4 + j) * ALD + r] = lo;
            }
        }
        __syncthreads();

        float accS[2][4][4];
#pragma unroll
        for (int mi = 0; mi < 2; mi++)
#pragma unroll
            for (int i = 0; i < 4; i++)
#pragma unroll
                for (int j = 0; j < 4; j++) accS[mi][i][j] = 0.f;

#pragma unroll
        for (int kk = 0; kk < 4; kk++) {
            uint32_t ah[2][4], al[2][4], bh[4][2], bl[4][2];
#pragma unroll
            for (int mi = 0; mi < 2; mi++) {
                const uint32_t aoff =
                    (uint32_t)((a_row_b + mi * 16) * ALD + kk * 16 + a_colsel) * 2;
                ldm4(ah[mi], sbA + A_QH * 2 + aoff);
                ldm4(al[mi], sbA + A_QL * 2 + aoff);
            }
#pragma unroll
            for (int p = 0; p < 2; p++) {
                const uint32_t boff =
                    (uint32_t)((b_row0 + p * 16) * ALD + kk * 16 + b_colsel) * 2;
                uint32_t th[4], tl[4];
                ldm4(th, sbA + A_KH * 2 + boff);
                ldm4(tl, sbA + A_KL * 2 + boff);
                bh[p * 2][0] = th[0]; bh[p * 2][1] = th[1];
                bh[p * 2 + 1][0] = th[2]; bh[p * 2 + 1][1] = th[3];
                bl[p * 2][0] = tl[0]; bl[p * 2][1] = tl[1];
                bl[p * 2 + 1][0] = tl[2]; bl[p * 2 + 1][1] = tl[3];
            }
#pragma unroll
            for (int mi = 0; mi < 2; mi++)
#pragma unroll
                for (int nt = 0; nt < 4; nt++) {
                    mma16816(accS[mi][nt], ah[mi], bh[nt]);
                    mma16816(accS[mi][nt], ah[mi], bl[nt]);
                    mma16816(accS[mi][nt], al[mi], bh[nt]);
                }
        }

#pragma unroll
        for (int mi = 0; mi < 2; mi++) {
            const int rr1 = wm * 32 + mi * 16 + trow;
            const int qi1 = q0 + rr1;
            const int qi2 = qi1 + 8;
#pragma unroll
            for (int nt = 0; nt < 4; nt++) {
                const int c = wn * 32 + nt * 8 + tcol;
                const int ja = j0 + c, jb = ja + 1;
                bool ok;
                ok = (ja <= qi1) && (qi1 - ja < win);
                Ss[rr1 * 64 + c]           = ok ? accS[mi][nt][0] * 0.125f : -INFINITY;
                ok = (jb <= qi1) && (qi1 - jb < win);
                Ss[rr1 * 64 + c + 1]       = ok ? accS[mi][nt][1] * 0.125f : -INFINITY;
                ok = (ja <= qi2) && (qi2 - ja < win);
                Ss[(rr1 + 8) * 64 + c]     = ok ? accS[mi][nt][2] * 0.125f : -INFINITY;
                ok = (jb <= qi2) && (qi2 - jb < win);
                Ss[(rr1 + 8) * 64 + c + 1] = ok ? accS[mi][nt][3] * 0.125f : -INFINITY;
            }
        }
        __syncthreads();

        {
            const int row = tid >> 1;
            const int part = tid & 1;
            float* srow = &Ss[row * 64 + part * 32];
            float tm = -INFINITY;
#pragma unroll
            for (int c = 0; c < 32; c++) tm = fmaxf(tm, srow[c]);
            tm = fmaxf(tm, __shfl_xor_sync(0xffffffffu, tm, 1));

            const float mold = m_s[row];
            const float nm = fmaxf(mold, tm);
            float scale;
            float psum = 0.f;
            if (nm == -INFINITY) {
                scale = 1.f;
#pragma unroll
                for (int c = 0; c < 32; c++) srow[c] = 0.f;
            } else {
                scale = expf(mold - nm);
#pragma unroll
                for (int c = 0; c < 32; c++) {
                    const float p = expf(srow[c] - nm);
                    srow[c] = p;
                    psum += p;
                }
            }
            psum += __shfl_xor_sync(0xffffffffu, psum, 1);
            if (part == 0) {
                m_s[row] = nm;
                l_s[row] = l_s[row] * scale + psum;
                sc_s[row] = scale;
            }
        }
        __syncthreads();

#pragma unroll
        for (int mi = 0; mi < 2; mi++) {
            const int rr1 = wm * 32 + mi * 16 + trow;
            const float s1 = sc_s[rr1];
            const float s2 = sc_s[rr1 + 8];
#pragma unroll
            for (int nt = 0; nt < 4; nt++) {
                accO[mi][nt][0] *= s1; accO[mi][nt][1] *= s1;
                accO[mi][nt][2] *= s2; accO[mi][nt][3] *= s2;
            }
        }
        for (int i = tid; i < QT * 16; i += 256) {
            const int r = i >> 4;
            const int c4 = (i & 15) * 4;
            const float4 pv = *(const float4*)&Ss[r * 64 + c4];
            const float pa[4] = {pv.x, pv.y, pv.z, pv.w};
#pragma unroll
            for (int j = 0; j < 4; j++) {
                bf16 hi, lo;
                split_f32(pa[j], hi, lo);
                sb[A_PH + r * ALD + c4 + j] = hi;
                sb[A_PL + r * ALD + c4 + j] = lo;
            }
        }
        __syncthreads();

#pragma unroll
        for (int kk = 0; kk < 4; kk++) {
            uint32_t ah[2][4], al[2][4], bh[4][2], bl[4][2];
#pragma unroll
            for (int mi = 0; mi < 2; mi++) {
                const uint32_t aoff =
                    (uint32_t)((a_row_b + mi * 16) * ALD + kk * 16 + a_colsel) * 2;
                ldm4(ah[mi], sbA + A_PH * 2 + aoff);
                ldm4(al[mi], sbA + A_PL * 2 + aoff);
            }
#pragma unroll
            for (int p = 0; p < 2; p++) {
                const uint32_t boff =
                    (uint32_t)((b_row0 + p * 16) * ALD + kk * 16 + b_colsel) * 2;
                uint32_t th[4], tl[4];
                ldm4(th, sbA + A_VH * 2 + boff);
                ldm4(tl, sbA + A_VL * 2 + boff);
                bh[p * 2][0] = th[0]; bh[p * 2][1] = th[1];
                bh[p * 2 + 1][0] = th[2]; bh[p * 2 + 1][1] = th[3];
                bl[p * 2][0] = tl[0]; bl[p * 2][1] = tl[1];
                bl[p * 2 + 1][0] = tl[2]; bl[p * 2 + 1][1] = tl[3];
            }
#pragma unroll
            for (int mi = 0; mi < 2; mi++)
#pragma unroll
                for (int nt = 0; nt < 4; nt++) {
                    mma16816(accO[mi][nt], ah[mi], bh[nt]);
                    mma16816(accO[mi][nt], ah[mi], bl[nt]);
                    mma16816(accO[mi][nt], al[mi], bh[nt]);
                }
        }
        __syncthreads();
    }

#pragma unroll
    for (int mi = 0; mi < 2; mi++) {
        const int rr1 = wm * 32 + mi * 16 + trow;
        const float li1 = 1.f / l_s[rr1];
        const float li2 = 1.f / l_s[rr1 + 8];
        const size_t o1 = ((size_t)(b * LL + q0 + rr1)) * DD + h * HD;
        const size_t o2 = o1 + (size_t)8 * DD;
#pragma unroll
        for (int nt = 0; nt < 4; nt++) {
            const int c = wn * 32 + nt * 8 + tcol;
            float vals[4] = {accO[mi][nt][0] * li1, accO[mi][nt][1] * li1,
                             accO[mi][nt][2] * li2, accO[mi][nt][3] * li2};
#pragma unroll
            for (int j = 0; j < 4; j++) if (!isfinite(vals[j])) vals[j] = 0.f;
            bf16 hi, lo;
            split_f32(vals[0], hi, lo); ohi[o1 + c] = hi;     olo[o1 + c] = lo;
            split_f32(vals[1], hi, lo); ohi[o1 + c + 1] = hi; olo[o1 + c + 1] = lo;
            split_f32(vals[2], hi, lo); ohi[o2 + c] = hi;     olo[o2 + c] = lo;
            split_f32(vals[3], hi, lo); ohi[o2 + c + 1] = hi; olo[o2 + c + 1] = lo;
        }
    }
}

// ---------------------------------------------------------------------------
// Launch
// ---------------------------------------------------------------------------
extern "C" void kernel_launch(void* const* d_in, const int* in_sizes, int n_in,
                              void* d_out, int out_size)
{
    const float* x    = (const float*)d_in[0];
    const float* wq_w = (const float*)d_in[1];
    const float* wq_b = (const float*)d_in[2];
    const float* wk_w = (const float*)d_in[3];
    const float* wk_b = (const float*)d_in[4];
    const float* wv_w = (const float*)d_in[5];
    const float* wv_b = (const float*)d_in[6];
    const float* wo_w = (const float*)d_in[7];
    const float* wo_b = (const float*)d_in[8];
    const float* q_nw = (const float*)d_in[9];
    const float* k_nw = (const float*)d_in[10];
    const float* s_nw = (const float*)d_in[11];
    const float* sp_nw= (const float*)d_in[12];
    const float* f_nw = (const float*)d_in[13];
    const float* fp_nw= (const float*)d_in[14];
    const float* w1_w = (const float*)d_in[15];
    const float* w1_b = (const float*)d_in[16];
    const float* w2_w = (const float*)d_in[17];
    const float* w2_b = (const float*)d_in[18];
    const float* w3_w = (const float*)d_in[19];
    const float* w3_b = (const float*)d_in[20];
    const int*   winp = (const int*)d_in[21];

    float* fbase = nullptr;
    cudaGetSymbolAddress((void**)&fbase, g_scratch);
    float* qkv = fbase;                       // [4096][3072]
    float* a   = fbase + 3 * SZ_D;
    float* h   = fbase + 4 * SZ_D;
    float* f   = fbase + 5 * SZ_D;

    float* bqkv = nullptr;
    cudaGetSymbolAddress((void**)&bqkv, g_bias_qkv);
    float* bffn = nullptr;
    cudaGetSymbolAddress((void**)&bffn, g_bias_ffn);

    bf16* bbase = nullptr;
    cudaGetSymbolAddress((void**)&bbase, g_bscratch);
    bf16* xn_h = bbase + 0 * BSZ_ACT;
    bf16* xn_l = bbase + 1 * BSZ_ACT;
    bf16* at_h = bbase + 2 * BSZ_ACT;
    bf16* at_l = bbase + 3 * BSZ_ACT;
    bf16* hn_h = bbase + 4 * BSZ_ACT;
    bf16* hn_l = bbase + 5 * BSZ_ACT;
    bf16* g_h  = bbase + 6 * BSZ_ACT;
    bf16* g_l  = bbase + 6 * BSZ_ACT + BSZ_G;
    bf16* w_h  = bbase + 6 * BSZ_ACT + 2 * BSZ_G;
    bf16* w_l  = bbase + 6 * BSZ_ACT + 2 * BSZ_G + BSZ_W;

    float* out = (float*)d_out;

    cudaFuncSetAttribute(gemm_bf16x3,
                         cudaFuncAttributeMaxDynamicSharedMemorySize, GEMM_SMEM);
    cudaFuncSetAttribute(attn_mma_kernel,
                         cudaFuncAttributeMaxDynamicSharedMemorySize,
                         ATT_SMEM_BYTES);

    // biases for fused GEMMs
    bias_concat_k<<<(I2P + 255) / 256, 256>>>(wq_b, wk_b, wv_b, w1_b, w3_b,
                                              bqkv, bffn);

    // 1) xn = rmsnorm(x, seq_norm_w) -> bf16 split
    rmsnorm_split_k<DD, 256><<<NROWS, 256>>>(x, s_nw, xn_h, xn_l);

    // 2) fused QKV projection
    {
        const size_t wN8 = (size_t)DD * DD / 8;
        conv_split8_k<<<(int)((wN8 + 255) / 256), 256>>>(wq_w, w_h, w_l, DD, DD, DD, DD);
        conv_split8_k<<<(int)((wN8 + 255) / 256), 256>>>(wk_w, w_h + (size_t)1024 * 1024,
                                                         w_l + (size_t)1024 * 1024, DD, DD, DD, DD);
        conv_split8_k<<<(int)((wN8 + 255) / 256), 256>>>(wv_w, w_h + (size_t)2048 * 1024,
                                                         w_l + (size_t)2048 * 1024, DD, DD, DD, DD);
        dim3 grid(QKVD / 128, NROWS / 128);
        gemm_bf16x3<<<grid, 256, GEMM_SMEM>>>(xn_h, xn_l, w_h, w_l, bqkv, qkv,
                                              QKVD, DD, QKVD, 0, nullptr, nullptr, 0);
    }

    // 3) tensor-core attention (q/k rmsnorm fused) -> bf16 split output
    {
        dim3 grid(LL / QT, HH, BB);
        attn_mma_kernel<<<grid, 256, ATT_SMEM_BYTES>>>(qkv, qkv + 1024, qkv + 2048,
                                                       q_nw, k_nw,
                                                       at_h, at_l, winp, QKVD);
    }

    // 4) output projection
    {
        const size_t wN8 = (size_t)DD * DD / 8;
        conv_split8_k<<<(int)((wN8 + 255) / 256), 256>>>(wo_w, w_h, w_l, DD, DD, DD, DD);
        dim3 grid(DD / 128, NROWS / 128);
        gemm_bf16x3<<<grid, 256, GEMM_SMEM>>>(at_h, at_l, w_h, w_l, wo_b, a,
                                              DD, DD, DD, 0, nullptr, nullptr, 0);
    }

    // 5) h = x + rmsnorm(a, seq_post_norm_w)
    rmsnorm_k<DD, 256><<<NROWS, 256>>>(a, sp_nw, x, h);

    // 6) hn = rmsnorm(h, ffn_norm_w) -> bf16 split
    rmsnorm_split_k<DD, 256><<<NROWS, 256>>>(h, f_nw, hn_h, hn_l);

    // 7) fused interleaved w1/w3 GEMM with silu epilogue -> g (bf16 split)
    {
        const size_t wN8 = (size_t)I2P * DD / 8;
        conv_split_ilv8_k<<<(int)((wN8 + 255) / 256), 256>>>(w1_w, w3_w, w_h, w_l);
        dim3 grid(I2P / 128, NROWS / 128);
        gemm_bf16x3<<<grid, 256, GEMM_SMEM>>>(hn_h, hn_l, w_h, w_l, bffn, nullptr,
                                              I2P, DD, 0, 1, g_h, g_l, IKP);
    }

    // 8) f = g @ w2^T + b2  (K = IKP, weight K-padded)
    {
        const size_t wN8 = (size_t)DD * IKP / 8;
        conv_split8_k<<<(int)((wN8 + 255) / 256), 256>>>(w2_w, w_h, w_l,
                                                         DD, II, DD, IKP);
        dim3 grid(DD / 128, NROWS / 128);
        gemm_bf16x3<<<grid, 256, GEMM_SMEM>>>(g_h, g_l, w_h, w_l, w2_b, f,
                                              DD, IKP, DD, 0, nullptr, nullptr, 0);
    }

    // 9) out = h + rmsnorm(f, ffn_post_norm_w)
    rmsnorm_k<DD, 256><<<NROWS, 256>>>(f, fp_nw, h, out);
}

// round 15
// speedup vs baseline: 1.0509x; 1.0419x over previous
#include <cuda_runtime.h>
#include <cuda_bf16.h>
#include <math.h>
#include <stdint.h>

typedef __nv_bfloat16 bf16;

// ---------------------------------------------------------------------------
// Problem constants
// ---------------------------------------------------------------------------
#define BB 4
#define LL 1024
#define DD 1024
#define HH 16
#define HD 64
#define II 3280
#define I2 6560
#define I2P 6656               // I2 padded to 128
#define IKP 3328               // II padded to 128 (w2 K / g stride)
#define QKVD 3072
#define NROWS (BB * LL)        // 4096
#define EPSV 1e-5f

#define SZ_D ((size_t)NROWS * DD)

// fp32 scratch: qkv(3*SZ_D), a, h, f
__device__ float g_scratch[6 * SZ_D];
__device__ float g_bias_qkv[QKVD];
__device__ float g_bias_ffn[I2P];

// bf16 scratch (hi/lo pairs)
#define BSZ_ACT ((size_t)NROWS * DD)
#define BSZ_G   ((size_t)NROWS * IKP)
#define BSZ_W   ((size_t)I2P * 1024)
__device__ bf16 g_bscratch[6 * BSZ_ACT + 2 * BSZ_G + 2 * BSZ_W];

// ---------------------------------------------------------------------------
// helpers
// ---------------------------------------------------------------------------
__device__ __forceinline__ void split_f32(float v, bf16& hi, bf16& lo) {
    hi = __float2bfloat16(v);
    lo = __float2bfloat16(v - __bfloat162float(hi));
}

__device__ __forceinline__ void cpa16p(bf16* dst, const bf16* src, bool valid) {
    uint32_t d = (uint32_t)__cvta_generic_to_shared(dst);
    int sz = valid ? 16 : 0;
    asm volatile("cp.async.ca.shared.global [%0], [%1], 16, %2;\n"
                 :: "r"(d), "l"(src), "r"(sz));
}
__device__ __forceinline__ void cpa_commit() {
    asm volatile("cp.async.commit_group;\n" ::: "memory");
}
__device__ __forceinline__ void cpa_wait_all() {
    asm volatile("cp.async.wait_group 0;\n" ::: "memory");
}

__device__ __forceinline__ void ldm4(uint32_t* r, uint32_t addr) {
    asm volatile("ldmatrix.sync.aligned.m8n8.x4.shared.b16 {%0,%1,%2,%3}, [%4];\n"
                 : "=r"(r[0]), "=r"(r[1]), "=r"(r[2]), "=r"(r[3]) : "r"(addr));
}

__device__ __forceinline__ void mma16816(float* d, const uint32_t* a, const uint32_t* b) {
    asm volatile(
        "mma.sync.aligned.m16n8k16.row.col.f32.bf16.bf16.f32 "
        "{%0,%1,%2,%3}, {%4,%5,%6,%7}, {%8,%9}, {%0,%1,%2,%3};\n"
        : "+f"(d[0]), "+f"(d[1]), "+f"(d[2]), "+f"(d[3])
        : "r"(a[0]), "r"(a[1]), "r"(a[2]), "r"(a[3]), "r"(b[0]), "r"(b[1]));
}

__device__ __forceinline__ void store_split8(bf16* hi, bf16* lo, const float* v) {
    bf16 hbuf[8], lbuf[8];
#pragma unroll
    for (int i = 0; i < 8; i++) split_f32(v[i], hbuf[i], lbuf[i]);
    *(uint4*)hi = *(const uint4*)hbuf;
    *(uint4*)lo = *(const uint4*)lbuf;
}

// ---------------------------------------------------------------------------
// RMSNorm (fp32 out, optional residual)
// ---------------------------------------------------------------------------
template <int W, int T>
__global__ void rmsnorm_k(const float* __restrict__ in,
                          const float* __restrict__ w,
                          const float* __restrict__ resid,
                          float* __restrict__ out)
{
    constexpr int PER = W / T;
    const size_t row = blockIdx.x;
    const float* xr = in + row * (size_t)W;
    float vals[PER];
    float ss = 0.f;
#pragma unroll
    for (int i = 0; i < PER; i++) {
        float vv = xr[threadIdx.x + i * T];
        vv = fminf(fmaxf(vv, -10000.f), 10000.f);
        vals[i] = vv;
        ss += vv * vv;
    }
    __shared__ float red[T];
    red[threadIdx.x] = ss;
    __syncthreads();
#pragma unroll
    for (int s = T / 2; s > 0; s >>= 1) {
        if (threadIdx.x < s) red[threadIdx.x] += red[threadIdx.x + s];
        __syncthreads();
    }
    const float mean = red[0] / (float)W;
    const float inv = 1.f / sqrtf(fmaxf(mean, EPSV) + EPSV);
#pragma unroll
    for (int i = 0; i < PER; i++) {
        const int c = threadIdx.x + i * T;
        float o = vals[i] * inv * w[c];
        if (!isfinite(o)) o = 0.f;
        if (resid) o += resid[row * (size_t)W + c];
        out[row * (size_t)W + c] = o;
    }
}

// RMSNorm writing bf16 hi/lo split
template <int W, int T>
__global__ void rmsnorm_split_k(const float* __restrict__ in,
                                const float* __restrict__ w,
                                bf16* __restrict__ ohi,
                                bf16* __restrict__ olo)
{
    constexpr int PER = W / T;
    const size_t row = blockIdx.x;
    const float* xr = in + row * (size_t)W;
    float vals[PER];
    float ss = 0.f;
#pragma unroll
    for (int i = 0; i < PER; i++) {
        float vv = xr[threadIdx.x + i * T];
        vv = fminf(fmaxf(vv, -10000.f), 10000.f);
        vals[i] = vv;
        ss += vv * vv;
    }
    __shared__ float red[T];
    red[threadIdx.x] = ss;
    __syncthreads();
#pragma unroll
    for (int s = T / 2; s > 0; s >>= 1) {
        if (threadIdx.x < s) red[threadIdx.x] += red[threadIdx.x + s];
        __syncthreads();
    }
    const float mean = red[0] / (float)W;
    const float inv = 1.f / sqrtf(fmaxf(mean, EPSV) + EPSV);
#pragma unroll
    for (int i = 0; i < PER; i++) {
        const int c = threadIdx.x + i * T;
        float o = vals[i] * inv * w[c];
        if (!isfinite(o)) o = 0.f;
        bf16 hi, lo;
        split_f32(o, hi, lo);
        ohi[row * (size_t)W + c] = hi;
        olo[row * (size_t)W + c] = lo;
    }
}

// Fused: h = x + rmsnorm(a, wsp); hn = rmsnorm(h, wf) -> bf16 split.
// Writes h (fp32) and hn hi/lo. One pass, h stays in registers.
template <int W, int T>
__global__ void rmsnorm_fuse2_k(const float* __restrict__ a,
                                const float* __restrict__ wsp,
                                const float* __restrict__ x,
                                const float* __restrict__ wf,
                                float* __restrict__ hout,
                                bf16* __restrict__ ohi,
                                bf16* __restrict__ olo)
{
    constexpr int PER = W / T;
    const size_t row = blockIdx.x;
    const float* ar = a + row * (size_t)W;
    float vals[PER];
    float ss = 0.f;
#pragma unroll
    for (int i = 0; i < PER; i++) {
        float vv = ar[threadIdx.x + i * T];
        vv = fminf(fmaxf(vv, -10000.f), 10000.f);
        vals[i] = vv;
        ss += vv * vv;
    }
    __shared__ float red[T];
    red[threadIdx.x] = ss;
    __syncthreads();
#pragma unroll
    for (int s = T / 2; s > 0; s >>= 1) {
        if (threadIdx.x < s) red[threadIdx.x] += red[threadIdx.x + s];
        __syncthreads();
    }
    const float inv1 = 1.f / sqrtf(fmaxf(red[0] / (float)W, EPSV) + EPSV);

    // h = x + norm(a); second reduction over clipped h
    float hvals[PER];
    float ss2 = 0.f;
#pragma unroll
    for (int i = 0; i < PER; i++) {
        const int c = threadIdx.x + i * T;
        float o = vals[i] * inv1 * wsp[c];
        if (!isfinite(o)) o = 0.f;
        const float hv = x[row * (size_t)W + c] + o;
        hout[row * (size_t)W + c] = hv;
        float hc = fminf(fmaxf(hv, -10000.f), 10000.f);
        hvals[i] = hc;
        ss2 += hc * hc;
    }
    __syncthreads();
    red[threadIdx.x] = ss2;
    __syncthreads();
#pragma unroll
    for (int s = T / 2; s > 0; s >>= 1) {
        if (threadIdx.x < s) red[threadIdx.x] += red[threadIdx.x + s];
        __syncthreads();
    }
    const float inv2 = 1.f / sqrtf(fmaxf(red[0] / (float)W, EPSV) + EPSV);
#pragma unroll
    for (int i = 0; i < PER; i++) {
        const int c = threadIdx.x + i * T;
        float o = hvals[i] * inv2 * wf[c];
        if (!isfinite(o)) o = 0.f;
        bf16 hi, lo;
        split_f32(o, hi, lo);
        ohi[row * (size_t)W + c] = hi;
        olo[row * (size_t)W + c] = lo;
    }
}

// ---------------------------------------------------------------------------
// Vectorized weight split (8 elems/thread)
// ---------------------------------------------------------------------------
__global__ void conv_split8_k(const float* __restrict__ src,
                              bf16* __restrict__ hi, bf16* __restrict__ lo,
                              int rows, int K0, int rowsPad, int KP)
{
    size_t i8 = ((size_t)blockIdx.x * blockDim.x + threadIdx.x) * 8;
    size_t n = (size_t)rowsPad * KP;
    if (i8 >= n) return;
    int r = (int)(i8 / KP);
    int c = (int)(i8 % KP);
    float v[8];
    if (r < rows && c + 8 <= K0) {
        const float* s = src + (size_t)r * K0 + c;
        *(float4*)&v[0] = *(const float4*)s;
        *(float4*)&v[4] = *(const float4*)(s + 4);
    } else {
#pragma unroll
        for (int i = 0; i < 8; i++) {
            int cc = c + i;
            v[i] = (r < rows && cc < K0) ? src[(size_t)r * K0 + cc] : 0.f;
        }
    }
    store_split8(hi + i8, lo + i8, v);
}

// Interleaved w1/w3 split
__global__ void conv_split_ilv8_k(const float* __restrict__ w1,
                                  const float* __restrict__ w3,
                                  bf16* __restrict__ hi, bf16* __restrict__ lo)
{
    size_t i8 = ((size_t)blockIdx.x * blockDim.x + threadIdx.x) * 8;
    size_t n = (size_t)I2P * DD;
    if (i8 >= n) return;
    int r = (int)(i8 / DD);
    int c = (int)(i8 % DD);
    int sr = r >> 1;
    float v[8];
    if (sr < II) {
        const float* s = ((r & 1) ? w3 : w1) + (size_t)sr * DD + c;
        *(float4*)&v[0] = *(const float4*)s;
        *(float4*)&v[4] = *(const float4*)(s + 4);
    } else {
#pragma unroll
        for (int i = 0; i < 8; i++) v[i] = 0.f;
    }
    store_split8(hi + i8, lo + i8, v);
}

// bias concat
__global__ void bias_concat_k(const float* qb, const float* kb, const float* vb,
                              const float* b1, const float* b3,
                              float* outQKV, float* outFFN)
{
    int i = blockIdx.x * blockDim.x + threadIdx.x;
    if (i < 1024) {
        outQKV[i] = qb[i];
        outQKV[1024 + i] = kb[i];
        outQKV[2048 + i] = vb[i];
    }
    if (i < I2P) {
        int sr = i >> 1;
        outFFN[i] = (sr < II) ? ((i & 1) ? b3[sr] : b1[sr]) : 0.f;
    }
}

// ---------------------------------------------------------------------------
// bf16x3 tensor-core GEMM (NT) — R14 config (2 CTAs/SM).
// ---------------------------------------------------------------------------
#define SKT 40
#define STAGE_ELEMS (128 * SKT)
#define GEMM_SMEM (2 * 4 * STAGE_ELEMS * 2)        // 81920 bytes

__global__ void __launch_bounds__(256, 2)
gemm_bf16x3(const bf16* __restrict__ Ah, const bf16* __restrict__ Al,
            const bf16* __restrict__ Bh, const bf16* __restrict__ Bl,
            const float* __restrict__ bias, float* __restrict__ C,
            int Mtot, int K, int ldc,
            int fuse_silu, bf16* __restrict__ Ghi, bf16* __restrict__ Glo,
            int ldg)
{
    extern __shared__ __align__(16) bf16 smem[];

    const int tid = threadIdx.x;
    const int lane = tid & 31;
    const int wid = tid >> 5;
    const int wm = wid & 1;
    const int wn = wid >> 1;

    const int bm = blockIdx.x * 128;
    const int bn = blockIdx.y * 128;

    const int ldr = tid >> 1;
    const int ldcol = (tid & 1) * 16;

    const bf16* gAh = Ah + (size_t)(bn + ldr) * K + ldcol;
    const bf16* gAl = Al + (size_t)(bn + ldr) * K + ldcol;
    const bool bvalid = (bm + ldr) < Mtot;
    const bf16* gBh = Bh + (size_t)(bm + ldr) * K + ldcol;
    const bf16* gBl = Bl + (size_t)(bm + ldr) * K + ldcol;

    const int s_off = ldr * SKT + ldcol;

    float acc[4][4][4];
#pragma unroll
    for (int i = 0; i < 4; i++)
#pragma unroll
        for (int j = 0; j < 4; j++)
#pragma unroll
            for (int r = 0; r < 4; r++) acc[i][j][r] = 0.f;

    const int nk = K >> 5;

    {
        bf16* s = smem;
        cpa16p(s + 0 * STAGE_ELEMS + s_off,     gAh,     true);
        cpa16p(s + 0 * STAGE_ELEMS + s_off + 8, gAh + 8, true);
        cpa16p(s + 1 * STAGE_ELEMS + s_off,     gAl,     true);
        cpa16p(s + 1 * STAGE_ELEMS + s_off + 8, gAl + 8, true);
        cpa16p(s + 2 * STAGE_ELEMS + s_off,     gBh,     bvalid);
        cpa16p(s + 2 * STAGE_ELEMS + s_off + 8, gBh + 8, bvalid);
        cpa16p(s + 3 * STAGE_ELEMS + s_off,     gBl,     bvalid);
        cpa16p(s + 3 * STAGE_ELEMS + s_off + 8, gBl + 8, bvalid);
    }
    cpa_commit();

    const int a_row = wm * 64 + (lane & 15);
    const int a_colsel = ((lane >> 4) & 1) << 3;
    const int b_row0 = wn * 32 + (((lane >> 4) & 1) << 3) + (lane & 7);
    const int b_colsel = ((lane >> 3) & 1) << 3;

    for (int kt = 0; kt < nk; kt++) {
        cpa_wait_all();
        __syncthreads();

        if (kt + 1 < nk) {
            bf16* s = smem + ((kt + 1) & 1) * (4 * STAGE_ELEMS);
            const int ko = (kt + 1) << 5;
            cpa16p(s + 0 * STAGE_ELEMS + s_off,     gAh + ko,     true);
            cpa16p(s + 0 * STAGE_ELEMS + s_off + 8, gAh + ko + 8, true);
            cpa16p(s + 1 * STAGE_ELEMS + s_off,     gAl + ko,     true);
            cpa16p(s + 1 * STAGE_ELEMS + s_off + 8, gAl + ko + 8, true);
            cpa16p(s + 2 * STAGE_ELEMS + s_off,     gBh + ko,     bvalid);
            cpa16p(s + 2 * STAGE_ELEMS + s_off + 8, gBh + ko + 8, bvalid);
            cpa16p(s + 3 * STAGE_ELEMS + s_off,     gBl + ko,     bvalid);
            cpa16p(s + 3 * STAGE_ELEMS + s_off + 8, gBl + ko + 8, bvalid);
        }
        cpa_commit();

        bf16* st = smem + (kt & 1) * (4 * STAGE_ELEMS);
        const uint32_t sAh = (uint32_t)__cvta_generic_to_shared(st + 0 * STAGE_ELEMS);
        const uint32_t sAl = (uint32_t)__cvta_generic_to_shared(st + 1 * STAGE_ELEMS);
        const uint32_t sBh = (uint32_t)__cvta_generic_to_shared(st + 2 * STAGE_ELEMS);
        const uint32_t sBl = (uint32_t)__cvta_generic_to_shared(st + 3 * STAGE_ELEMS);

#pragma unroll
        for (int ks = 0; ks < 2; ks++) {
            const int koff = ks * 16;
            uint32_t ah[4][4], al[4][4], bh[4][2], bl[4][2];
#pragma unroll
            for (int mi = 0; mi < 4; mi++) {
                const uint32_t off =
                    ((a_row + mi * 16) * SKT + koff + a_colsel) * 2;
                ldm4(ah[mi], sAh + off);
                ldm4(al[mi], sAl + off);
            }
#pragma unroll
            for (int p = 0; p < 2; p++) {
                const uint32_t off =
                    ((b_row0 + p * 16) * SKT + koff + b_colsel) * 2;
                uint32_t th[4], tl[4];
                ldm4(th, sBh + off);
                ldm4(tl, sBl + off);
                bh[p * 2][0] = th[0]; bh[p * 2][1] = th[1];
                bh[p * 2 + 1][0] = th[2]; bh[p * 2 + 1][1] = th[3];
                bl[p * 2][0] = tl[0]; bl[p * 2][1] = tl[1];
                bl[p * 2 + 1][0] = tl[2]; bl[p * 2 + 1][1] = tl[3];
            }
#pragma unroll
            for (int mi = 0; mi < 4; mi++)
#pragma unroll
                for (int ni = 0; ni < 4; ni++) {
                    mma16816(acc[mi][ni], ah[mi], bh[ni]);
                    mma16816(acc[mi][ni], ah[mi], bl[ni]);
                    mma16816(acc[mi][ni], al[mi], bh[ni]);
                }
        }
        __syncthreads();
    }

    const int trow = lane >> 2;
    const int tcol = (lane & 3) * 2;
    if (!fuse_silu) {
#pragma unroll
        for (int mi = 0; mi < 4; mi++) {
            const size_t r0 = (size_t)bn + wm * 64 + mi * 16 + trow;
#pragma unroll
            for (int ni = 0; ni < 4; ni++) {
                const int col = bm + wn * 32 + ni * 8 + tcol;
                if (col < Mtot) {
                    const float b0 = bias[col];
                    const float b1 = bias[col + 1];
                    float2 v0 = make_float2(acc[mi][ni][0] + b0, acc[mi][ni][1] + b1);
                    float2 v1 = make_float2(acc[mi][ni][2] + b0, acc[mi][ni][3] + b1);
                    *(float2*)&C[r0 * (size_t)ldc + col] = v0;
                    *(float2*)&C[(r0 + 8) * (size_t)ldc + col] = v1;
                }
            }
        }
    } else {
#pragma unroll
        for (int mi = 0; mi < 4; mi++) {
            const size_t r0 = (size_t)bn + wm * 64 + mi * 16 + trow;
#pragma unroll
            for (int ni = 0; ni < 4; ni++) {
                const int col = bm + wn * 32 + ni * 8 + tcol;   // even
                const int gcol = col >> 1;
                const float b0 = bias[col];
                const float b1 = bias[col + 1];
                {
                    const float z1 = acc[mi][ni][0] + b0;
                    const float z3 = acc[mi][ni][1] + b1;
                    const float g = (z1 / (1.f + expf(-z1))) * z3;
                    bf16 hi, lo;
                    split_f32(g, hi, lo);
                    Ghi[r0 * (size_t)ldg + gcol] = hi;
                    Glo[r0 * (size_t)ldg + gcol] = lo;
                }
                {
                    const float z1 = acc[mi][ni][2] + b0;
                    const float z3 = acc[mi][ni][3] + b1;
                    const float g = (z1 / (1.f + expf(-z1))) * z3;
                    bf16 hi, lo;
                    split_f32(g, hi, lo);
                    Ghi[(r0 + 8) * (size_t)ldg + gcol] = hi;
                    Glo[(r0 + 8) * (size_t)ldg + gcol] = lo;
                }
            }
        }
    }
}

// ---------------------------------------------------------------------------
// Tensor-core flash attention: QT=64 tile (2 CTAs/SM), fused q/k rmsnorm,
// bf16x3 mma, fp32 online softmax. 256 threads = 8 warps.
// ---------------------------------------------------------------------------
#define QT 64
#define ALD 72
#define A_QH 0
#define A_QL (QT * ALD)
#define A_KH (2 * QT * ALD)
#define A_KL (3 * QT * ALD)
#define A_VH (4 * QT * ALD)
#define A_VL (5 * QT * ALD)
#define A_PH (6 * QT * ALD)
#define A_PL (7 * QT * ALD)
#define A_BF_TOT (8 * QT * ALD)
#define ATT_SMEM_BYTES (A_BF_TOT * 2 + (QT * 64 + 3 * QT) * 4)   // 90880

__global__ void __launch_bounds__(256, 2)
attn_mma_kernel(const float* __restrict__ q, const float* __restrict__ k,
                const float* __restrict__ v,
                const float* __restrict__ qnw, const float* __restrict__ knw,
                bf16* __restrict__ ohi, bf16* __restrict__ olo,
                const int* __restrict__ winp, int qs)
{
    extern __shared__ __align__(16) char smraw[];
    bf16* sb = (bf16*)smraw;
    float* Ss  = (float*)(smraw + A_BF_TOT * 2);
    float* m_s = Ss + QT * 64;
    float* l_s = m_s + QT;
    float* sc_s = l_s + QT;

    const int q0 = blockIdx.x * QT;
    const int h  = blockIdx.y;
    const int b  = blockIdx.z;
    const int tid = threadIdx.x;
    const int lane = tid & 31;
    const int wid = tid >> 5;
    const int wm = wid & 3;
    const int wn = wid >> 2;
    const int win = *winp;

    const uint32_t sbA = (uint32_t)__cvta_generic_to_shared(sb);

    // Q load + fused per-head rmsnorm + split (16 lanes share a row)
    const size_t base_q = ((size_t)(b * LL + q0)) * qs + h * HD;
    for (int i = tid; i < QT * 16; i += 256) {
        const int r = i >> 4;
        const int c4 = (i & 15) * 4;
        const float4 qv = *(const float4*)&q[base_q + (size_t)r * qs + c4];
        float vv[4] = {qv.x, qv.y, qv.z, qv.w};
#pragma unroll
        for (int j = 0; j < 4; j++) vv[j] = fminf(fmaxf(vv[j], -10000.f), 10000.f);
        float ss = vv[0] * vv[0] + vv[1] * vv[1] + vv[2] * vv[2] + vv[3] * vv[3];
        ss += __shfl_xor_sync(0xffffffffu, ss, 1);
        ss += __shfl_xor_sync(0xffffffffu, ss, 2);
        ss += __shfl_xor_sync(0xffffffffu, ss, 4);
        ss += __shfl_xor_sync(0xffffffffu, ss, 8);
        const float inv = 1.f / sqrtf(fmaxf(ss / 64.f, EPSV) + EPSV);
#pragma unroll
        for (int j = 0; j < 4; j++) {
            float o = vv[j] * inv * qnw[c4 + j];
            if (!isfinite(o)) o = 0.f;
            bf16 hi, lo;
            split_f32(o, hi, lo);
            sb[A_QH + r * ALD + c4 + j] = hi;
            sb[A_QL + r * ALD + c4 + j] = lo;
        }
    }
    if (tid < QT) { m_s[tid] = -INFINITY; l_s[tid] = 0.f; }

    float accO[4][4];
#pragma unroll
    for (int i = 0; i < 4; i++)
#pragma unroll
        for (int j = 0; j < 4; j++) accO[i][j] = 0.f;

    int lo0 = q0 - win + 1;
    if (lo0 < 0) lo0 = 0;
    const int kt0 = lo0 >> 6;
    const int kt1 = q0 >> 6;

    const int a_row = wm * 16 + (lane & 15);
    const int a_colsel = ((lane >> 4) & 1) << 3;
    const int b_row0 = wn * 32 + (((lane >> 4) & 1) << 3) + (lane & 7);
    const int b_colsel = ((lane >> 3) & 1) << 3;
    const int trow = lane >> 2;
    const int tcol = (lane & 3) * 2;
    const int r1 = wm * 16 + trow;

    __syncthreads();

    for (int kt = kt0; kt <= kt1; kt++) {
        const int j0 = kt << 6;
        const size_t base_k = ((size_t)(b * LL + j0)) * qs + h * HD;

        // K load + fused rmsnorm + split; V load transposed + split
        for (int i = tid; i < 64 * 16; i += 256) {
            const int r = i >> 4;
            const int c4 = (i & 15) * 4;
            const float4 kv = *(const float4*)&k[base_k + (size_t)r * qs + c4];
            float kk[4] = {kv.x, kv.y, kv.z, kv.w};
#pragma unroll
            for (int j = 0; j < 4; j++) kk[j] = fminf(fmaxf(kk[j], -10000.f), 10000.f);
            float ss = kk[0] * kk[0] + kk[1] * kk[1] + kk[2] * kk[2] + kk[3] * kk[3];
            ss += __shfl_xor_sync(0xffffffffu, ss, 1);
            ss += __shfl_xor_sync(0xffffffffu, ss, 2);
            ss += __shfl_xor_sync(0xffffffffu, ss, 4);
            ss += __shfl_xor_sync(0xffffffffu, ss, 8);
            const float inv = 1.f / sqrtf(fmaxf(ss / 64.f, EPSV) + EPSV);
            const float4 vvv = *(const float4*)&v[base_k + (size_t)r * qs + c4];
            const float va[4] = {vvv.x, vvv.y, vvv.z, vvv.w};
#pragma unroll
            for (int j = 0; j < 4; j++) {
                float o = kk[j] * inv * knw[c4 + j];
                if (!isfinite(o)) o = 0.f;
                bf16 hi, lo;
                split_f32(o, hi, lo);
                sb[A_KH + r * ALD + c4 + j] = hi;
                sb[A_KL + r * ALD + c4 + j] = lo;
                split_f32(va[j], hi, lo);
                sb[A_VH + (c4 + j) * ALD + r] = hi;
                sb[A_VL + (c4 + j) * ALD + r] = lo;
            }
        }
        __syncthreads();

        // S = Q K^T (bf16x3)
        float accS[4][4];
#pragma unroll
        for (int i = 0; i < 4; i++)
#pragma unroll
            for (int j = 0; j < 4; j++) accS[i][j] = 0.f;

#pragma unroll
        for (int kk = 0; kk < 4; kk++) {
            uint32_t ah[4], al[4], bh[4][2], bl[4][2];
            const uint32_t aoff = (uint32_t)(a_row * ALD + kk * 16 + a_colsel) * 2;
            ldm4(ah, sbA + A_QH * 2 + aoff);
            ldm4(al, sbA + A_QL * 2 + aoff);
#pragma unroll
            for (int p = 0; p < 2; p++) {
                const uint32_t boff =
                    (uint32_t)((b_row0 + p * 16) * ALD + kk * 16 + b_colsel) * 2;
                uint32_t th[4], tl[4];
                ldm4(th, sbA + A_KH * 2 + boff);
                ldm4(tl, sbA + A_KL * 2 + boff);
                bh[p * 2][0] = th[0]; bh[p * 2][1] = th[1];
                bh[p * 2 + 1][0] = th[2]; bh[p * 2 + 1][1] = th[3];
                bl[p * 2][0] = tl[0]; bl[p * 2][1] = tl[1];
                bl[p * 2 + 1][0] = tl[2]; bl[p * 2 + 1][1] = tl[3];
            }
#pragma unroll
            for (int nt = 0; nt < 4; nt++) {
                mma16816(accS[nt], ah, bh[nt]);
                mma16816(accS[nt], ah, bl[nt]);
                mma16816(accS[nt], al, bh[nt]);
            }
        }

        // masked scaled S -> Ss
        {
            const int qi1 = q0 + r1;
            const int qi2 = qi1 + 8;
#pragma unroll
            for (int nt = 0; nt < 4; nt++) {
                const int c = wn * 32 + nt * 8 + tcol;
                const int ja = j0 + c, jb = ja + 1;
                bool ok;
                ok = (ja <= qi1) && (qi1 - ja < win);
                Ss[r1 * 64 + c]           = ok ? accS[nt][0] * 0.125f : -INFINITY;
                ok = (jb <= qi1) && (qi1 - jb < win);
                Ss[r1 * 64 + c + 1]       = ok ? accS[nt][1] * 0.125f : -INFINITY;
                ok = (ja <= qi2) && (qi2 - ja < win);
                Ss[(r1 + 8) * 64 + c]     = ok ? accS[nt][2] * 0.125f : -INFINITY;
                ok = (jb <= qi2) && (qi2 - jb < win);
                Ss[(r1 + 8) * 64 + c + 1] = ok ? accS[nt][3] * 0.125f : -INFINITY;
            }
        }
        __syncthreads();

        // online softmax: 4 threads per row, 16 cols each
        {
            const int row = tid >> 2;
            const int part = tid & 3;
            float* srow = &Ss[row * 64 + part * 16];
            float tm = -INFINITY;
#pragma unroll
            for (int c = 0; c < 16; c++) tm = fmaxf(tm, srow[c]);
            tm = fmaxf(tm, __shfl_xor_sync(0xffffffffu, tm, 1));
            tm = fmaxf(tm, __shfl_xor_sync(0xffffffffu, tm, 2));

            const float mold = m_s[row];
            const float nm = fmaxf(mold, tm);
            float scale;
            float psum = 0.f;
            if (nm == -INFINITY) {
                scale = 1.f;
#pragma unroll
                for (int c = 0; c < 16; c++) srow[c] = 0.f;
            } else {
                scale = expf(mold - nm);
#pragma unroll
                for (int c = 0; c < 16; c++) {
                    const float p = expf(srow[c] - nm);
                    srow[c] = p;
                    psum += p;
                }
            }
            psum += __shfl_xor_sync(0xffffffffu, psum, 1);
            psum += __shfl_xor_sync(0xffffffffu, psum, 2);
            if (part == 0) {
                m_s[row] = nm;
                l_s[row] = l_s[row] * scale + psum;
                sc_s[row] = scale;
            }
        }
        __syncthreads();

        // rescale accO; convert P -> bf16 hi/lo
        {
            const float s1 = sc_s[r1];
            const float s2 = sc_s[r1 + 8];
#pragma unroll
            for (int nt = 0; nt < 4; nt++) {
                accO[nt][0] *= s1; accO[nt][1] *= s1;
                accO[nt][2] *= s2; accO[nt][3] *= s2;
            }
        }
        for (int i = tid; i < QT * 16; i += 256) {
            const int r = i >> 4;
            const int c4 = (i & 15) * 4;
            const float4 pv = *(const float4*)&Ss[r * 64 + c4];
            const float pa[4] = {pv.x, pv.y, pv.z, pv.w};
#pragma unroll
            for (int j = 0; j < 4; j++) {
                bf16 hi, lo;
                split_f32(pa[j], hi, lo);
                sb[A_PH + r * ALD + c4 + j] = hi;
                sb[A_PL + r * ALD + c4 + j] = lo;
            }
        }
        __syncthreads();

        // O += P V (bf16x3)
#pragma unroll
        for (int kk = 0; kk < 4; kk++) {
            uint32_t ah[4], al[4], bh[4][2], bl[4][2];
            const uint32_t aoff = (uint32_t)(a_row * ALD + kk * 16 + a_colsel) * 2;
            ldm4(ah, sbA + A_PH * 2 + aoff);
            ldm4(al, sbA + A_PL * 2 + aoff);
#pragma unroll
            for (int p = 0; p < 2; p++) {
                const uint32_t boff =
                    (uint32_t)((b_row0 + p * 16) * ALD + kk * 16 + b_colsel) * 2;
                uint32_t th[4], tl[4];
                ldm4(th, sbA + A_VH * 2 + boff);
                ldm4(tl, sbA + A_VL * 2 + boff);
                bh[p * 2][0] = th[0]; bh[p * 2][1] = th[1];
                bh[p * 2 + 1][0] = th[2]; bh[p * 2 + 1][1] = th[3];
                bl[p * 2][0] = tl[0]; bl[p * 2][1] = tl[1];
                bl[p * 2 + 1][0] = tl[2]; bl[p * 2 + 1][1] = tl[3];
            }
#pragma unroll
            for (int nt = 0; nt < 4; nt++) {
                mma16816(accO[nt], ah, bh[nt]);
                mma16816(accO[nt], ah, bl[nt]);
                mma16816(accO[nt], al, bh[nt]);
            }
        }
        __syncthreads();
    }

    // epilogue
    {
        const float li1 = 1.f / l_s[r1];
        const float li2 = 1.f / l_s[r1 + 8];
        const size_t o1 = ((size_t)(b * LL + q0 + r1)) * DD + h * HD;
        const size_t o2 = o1 + (size_t)8 * DD;
#pragma unroll
        for (int nt = 0; nt < 4; nt++) {
            const int c = wn * 32 + nt * 8 + tcol;
            float vals[4] = {accO[nt][0] * li1, accO[nt][1] * li1,
                             accO[nt][2] * li2, accO[nt][3] * li2};
#pragma unroll
            for (int j = 0; j < 4; j++) if (!isfinite(vals[j])) vals[j] = 0.f;
            bf16 hi, lo;
            split_f32(vals[0], hi, lo); ohi[o1 + c] = hi;     olo[o1 + c] = lo;
            split_f32(vals[1], hi, lo); ohi[o1 + c + 1] = hi; olo[o1 + c + 1] = lo;
            split_f32(vals[2], hi, lo); ohi[o2 + c] = hi;     olo[o2 + c] = lo;
            split_f32(vals[3], hi, lo); ohi[o2 + c + 1] = hi; olo[o2 + c + 1] = lo;
        }
    }
}

// ---------------------------------------------------------------------------
// Launch
// ---------------------------------------------------------------------------
extern "C" void kernel_launch(void* const* d_in, const int* in_sizes, int n_in,
                              void* d_out, int out_size)
{
    const float* x    = (const float*)d_in[0];
    const float* wq_w = (const float*)d_in[1];
    const float* wq_b = (const float*)d_in[2];
    const float* wk_w = (const float*)d_in[3];
    const float* wk_b = (const float*)d_in[4];
    const float* wv_w = (const float*)d_in[5];
    const float* wv_b = (const float*)d_in[6];
    const float* wo_w = (const float*)d_in[7];
    const float* wo_b = (const float*)d_in[8];
    const float* q_nw = (const float*)d_in[9];
    const float* k_nw = (const float*)d_in[10];
    const float* s_nw = (const float*)d_in[11];
    const float* sp_nw= (const float*)d_in[12];
    const float* f_nw = (const float*)d_in[13];
    const float* fp_nw= (const float*)d_in[14];
    const float* w1_w = (const float*)d_in[15];
    const float* w1_b = (const float*)d_in[16];
    const float* w2_w = (const float*)d_in[17];
    const float* w2_b = (const float*)d_in[18];
    const float* w3_w = (const float*)d_in[19];
    const float* w3_b = (const float*)d_in[20];
    const int*   winp = (const int*)d_in[21];

    float* fbase = nullptr;
    cudaGetSymbolAddress((void**)&fbase, g_scratch);
    float* qkv = fbase;                       // [4096][3072]
    float* a   = fbase + 3 * SZ_D;
    float* h   = fbase + 4 * SZ_D;
    float* f   = fbase + 5 * SZ_D;

    float* bqkv = nullptr;
    cudaGetSymbolAddress((void**)&bqkv, g_bias_qkv);
    float* bffn = nullptr;
    cudaGetSymbolAddress((void**)&bffn, g_bias_ffn);

    bf16* bbase = nullptr;
    cudaGetSymbolAddress((void**)&bbase, g_bscratch);
    bf16* xn_h = bbase + 0 * BSZ_ACT;
    bf16* xn_l = bbase + 1 * BSZ_ACT;
    bf16* at_h = bbase + 2 * BSZ_ACT;
    bf16* at_l = bbase + 3 * BSZ_ACT;
    bf16* hn_h = bbase + 4 * BSZ_ACT;
    bf16* hn_l = bbase + 5 * BSZ_ACT;
    bf16* g_h  = bbase + 6 * BSZ_ACT;
    bf16* g_l  = bbase + 6 * BSZ_ACT + BSZ_G;
    bf16* w_h  = bbase + 6 * BSZ_ACT + 2 * BSZ_G;
    bf16* w_l  = bbase + 6 * BSZ_ACT + 2 * BSZ_G + BSZ_W;

    float* out = (float*)d_out;

    cudaFuncSetAttribute(gemm_bf16x3,
                         cudaFuncAttributeMaxDynamicSharedMemorySize, GEMM_SMEM);
    cudaFuncSetAttribute(attn_mma_kernel,
                         cudaFuncAttributeMaxDynamicSharedMemorySize,
                         ATT_SMEM_BYTES);

    // biases for fused GEMMs
    bias_concat_k<<<(I2P + 255) / 256, 256>>>(wq_b, wk_b, wv_b, w1_b, w3_b,
                                              bqkv, bffn);

    // 1) xn = rmsnorm(x, seq_norm_w) -> bf16 split
    rmsnorm_split_k<DD, 256><<<NROWS, 256>>>(x, s_nw, xn_h, xn_l);

    // 2) fused QKV projection
    {
        const size_t wN8 = (size_t)DD * DD / 8;
        conv_split8_k<<<(int)((wN8 + 255) / 256), 256>>>(wq_w, w_h, w_l, DD, DD, DD, DD);
        conv_split8_k<<<(int)((wN8 + 255) / 256), 256>>>(wk_w, w_h + (size_t)1024 * 1024,
                                                         w_l + (size_t)1024 * 1024, DD, DD, DD, DD);
        conv_split8_k<<<(int)((wN8 + 255) / 256), 256>>>(wv_w, w_h + (size_t)2048 * 1024,
                                                         w_l + (size_t)2048 * 1024, DD, DD, DD, DD);
        dim3 grid(QKVD / 128, NROWS / 128);
        gemm_bf16x3<<<grid, 256, GEMM_SMEM>>>(xn_h, xn_l, w_h, w_l, bqkv, qkv,
                                              QKVD, DD, QKVD, 0, nullptr, nullptr, 0);
    }

    // 3) tensor-core attention (q/k rmsnorm fused) -> bf16 split output
    {
        dim3 grid(LL / QT, HH, BB);
        attn_mma_kernel<<<grid, 256, ATT_SMEM_BYTES>>>(qkv, qkv + 1024, qkv + 2048,
                                                       q_nw, k_nw,
                                                       at_h, at_l, winp, QKVD);
    }

    // 4) output projection
    {
        const size_t wN8 = (size_t)DD * DD / 8;
        conv_split8_k<<<(int)((wN8 + 255) / 256), 256>>>(wo_w, w_h, w_l, DD, DD, DD, DD);
        dim3 grid(DD / 128, NROWS / 128);
        gemm_bf16x3<<<grid, 256, GEMM_SMEM>>>(at_h, at_l, w_h, w_l, wo_b, a,
                                              DD, DD, DD, 0, nullptr, nullptr, 0);
    }

    // 5+6) fused: h = x + rmsnorm(a, sp_nw); hn = rmsnorm(h, f_nw) split
    rmsnorm_fuse2_k<DD, 256><<<NROWS, 256>>>(a, sp_nw, x, f_nw, h, hn_h, hn_l);

    // 7) fused interleaved w1/w3 GEMM with silu epilogue -> g (bf16 split)
    {
        const size_t wN8 = (size_t)I2P * DD / 8;
        conv_split_ilv8_k<<<(int)((wN8 + 255) / 256), 256>>>(w1_w, w3_w, w_h, w_l);
        dim3 grid(I2P / 128, NROWS / 128);
        gemm_bf16x3<<<grid, 256, GEMM_SMEM>>>(hn_h, hn_l, w_h, w_l, bffn, nullptr,
                                              I2P, DD, 0, 1, g_h, g_l, IKP);
    }

    // 8) f = g @ w2^T + b2  (K = IKP, weight K-padded)
    {
        const size_t wN8 = (size_t)DD * IKP / 8;
        conv_split8_k<<<(int)((wN8 + 255) / 256), 256>>>(w2_w, w_h, w_l,
                                                         DD, II, DD, IKP);
        dim3 grid(DD / 128, NROWS / 128);
        gemm_bf16x3<<<grid, 256, GEMM_SMEM>>>(g_h, g_l, w_h, w_l, w2_b, f,
                                              DD, IKP, DD, 0, nullptr, nullptr, 0);
    }

    // 9) out = h + rmsnorm(f, ffn_post_norm_w)
    rmsnorm_k<DD, 256><<<NROWS, 256>>>(f, fp_nw, h, out);
}

// round 16
// speedup vs baseline: 1.2883x; 1.2260x over previous
#include <cuda_runtime.h>
#include <cuda_bf16.h>
#include <cuda_fp16.h>
#include <math.h>
#include <stdint.h>

typedef __nv_bfloat16 bf16;
typedef __half f16;

// ---------------------------------------------------------------------------
// Problem constants
// ---------------------------------------------------------------------------
#define BB 4
#define LL 1024
#define DD 1024
#define HH 16
#define HD 64
#define II 3280
#define I2 6560
#define I2P 6656               // I2 padded to 128
#define IKP 3328               // II padded to 128 (w2 K / g stride)
#define QKVD 3072
#define NROWS (BB * LL)        // 4096
#define EPSV 1e-5f

#define SZ_D ((size_t)NROWS * DD)

// fp32 scratch: qkv(3*SZ_D), a, h, f
__device__ float g_scratch[6 * SZ_D];
__device__ float g_bias_qkv[QKVD];
__device__ float g_bias_ffn[I2P];

// fp16 scratch: activation hi/lo pairs + single-precision-weight arrays
#define BSZ_ACT ((size_t)NROWS * DD)
#define BSZ_G   ((size_t)NROWS * IKP)
#define BSZ_W   ((size_t)I2P * 1024)
__device__ f16 g_hscratch[6 * BSZ_ACT + 2 * BSZ_G + BSZ_W];

// ---------------------------------------------------------------------------
// helpers
// ---------------------------------------------------------------------------
__device__ __forceinline__ void split_h(float v, f16& hi, f16& lo) {
    hi = __float2half_rn(v);
    lo = __float2half_rn(v - __half2float(hi));
}
__device__ __forceinline__ void split_bf(float v, bf16& hi, bf16& lo) {
    hi = __float2bfloat16(v);
    lo = __float2bfloat16(v - __bfloat162float(hi));
}

__device__ __forceinline__ void cpa16p(const void* dst, const void* src, bool valid) {
    uint32_t d = (uint32_t)__cvta_generic_to_shared(dst);
    int sz = valid ? 16 : 0;
    asm volatile("cp.async.ca.shared.global [%0], [%1], 16, %2;\n"
                 :: "r"(d), "l"(src), "r"(sz));
}
__device__ __forceinline__ void cpa_commit() {
    asm volatile("cp.async.commit_group;\n" ::: "memory");
}
__device__ __forceinline__ void cpa_wait_all() {
    asm volatile("cp.async.wait_group 0;\n" ::: "memory");
}

__device__ __forceinline__ void ldm4(uint32_t* r, uint32_t addr) {
    asm volatile("ldmatrix.sync.aligned.m8n8.x4.shared.b16 {%0,%1,%2,%3}, [%4];\n"
                 : "=r"(r[0]), "=r"(r[1]), "=r"(r[2]), "=r"(r[3]) : "r"(addr));
}

// fp16 mma, fp32 accumulate
__device__ __forceinline__ void mma_h(float* d, const uint32_t* a, const uint32_t* b) {
    asm volatile(
        "mma.sync.aligned.m16n8k16.row.col.f32.f16.f16.f32 "
        "{%0,%1,%2,%3}, {%4,%5,%6,%7}, {%8,%9}, {%0,%1,%2,%3};\n"
        : "+f"(d[0]), "+f"(d[1]), "+f"(d[2]), "+f"(d[3])
        : "r"(a[0]), "r"(a[1]), "r"(a[2]), "r"(a[3]), "r"(b[0]), "r"(b[1]));
}
// bf16 mma (attention)
__device__ __forceinline__ void mma_bf(float* d, const uint32_t* a, const uint32_t* b) {
    asm volatile(
        "mma.sync.aligned.m16n8k16.row.col.f32.bf16.bf16.f32 "
        "{%0,%1,%2,%3}, {%4,%5,%6,%7}, {%8,%9}, {%0,%1,%2,%3};\n"
        : "+f"(d[0]), "+f"(d[1]), "+f"(d[2]), "+f"(d[3])
        : "r"(a[0]), "r"(a[1]), "r"(a[2]), "r"(a[3]), "r"(b[0]), "r"(b[1]));
}

__device__ __forceinline__ void store8h(f16* dst, const float* v) {
    f16 buf[8];
#pragma unroll
    for (int i = 0; i < 8; i++) buf[i] = __float2half_rn(v[i]);
    *(uint4*)dst = *(const uint4*)buf;
}

// ---------------------------------------------------------------------------
// RMSNorm (fp32 out, optional residual) — final output step
// ---------------------------------------------------------------------------
template <int W, int T>
__global__ void rmsnorm_k(const float* __restrict__ in,
                          const float* __restrict__ w,
                          const float* __restrict__ resid,
                          float* __restrict__ out)
{
    constexpr int PER = W / T;
    const size_t row = blockIdx.x;
    const float* xr = in + row * (size_t)W;
    float vals[PER];
    float ss = 0.f;
#pragma unroll
    for (int i = 0; i < PER; i++) {
        float vv = xr[threadIdx.x + i * T];
        vv = fminf(fmaxf(vv, -10000.f), 10000.f);
        vals[i] = vv;
        ss += vv * vv;
    }
    __shared__ float red[T];
    red[threadIdx.x] = ss;
    __syncthreads();
#pragma unroll
    for (int s = T / 2; s > 0; s >>= 1) {
        if (threadIdx.x < s) red[threadIdx.x] += red[threadIdx.x + s];
        __syncthreads();
    }
    const float mean = red[0] / (float)W;
    const float inv = 1.f / sqrtf(fmaxf(mean, EPSV) + EPSV);
#pragma unroll
    for (int i = 0; i < PER; i++) {
        const int c = threadIdx.x + i * T;
        float o = vals[i] * inv * w[c];
        if (!isfinite(o)) o = 0.f;
        if (resid) o += resid[row * (size_t)W + c];
        out[row * (size_t)W + c] = o;
    }
}

// RMSNorm -> fp16 hi/lo split
template <int W, int T>
__global__ void rmsnorm_split_k(const float* __restrict__ in,
                                const float* __restrict__ w,
                                f16* __restrict__ ohi,
                                f16* __restrict__ olo)
{
    constexpr int PER = W / T;
    const size_t row = blockIdx.x;
    const float* xr = in + row * (size_t)W;
    float vals[PER];
    float ss = 0.f;
#pragma unroll
    for (int i = 0; i < PER; i++) {
        float vv = xr[threadIdx.x + i * T];
        vv = fminf(fmaxf(vv, -10000.f), 10000.f);
        vals[i] = vv;
        ss += vv * vv;
    }
    __shared__ float red[T];
    red[threadIdx.x] = ss;
    __syncthreads();
#pragma unroll
    for (int s = T / 2; s > 0; s >>= 1) {
        if (threadIdx.x < s) red[threadIdx.x] += red[threadIdx.x + s];
        __syncthreads();
    }
    const float mean = red[0] / (float)W;
    const float inv = 1.f / sqrtf(fmaxf(mean, EPSV) + EPSV);
#pragma unroll
    for (int i = 0; i < PER; i++) {
        const int c = threadIdx.x + i * T;
        float o = vals[i] * inv * w[c];
        if (!isfinite(o)) o = 0.f;
        f16 hi, lo;
        split_h(o, hi, lo);
        ohi[row * (size_t)W + c] = hi;
        olo[row * (size_t)W + c] = lo;
    }
}

// Fused: h = x + rmsnorm(a, wsp); hn = rmsnorm(h, wf) -> fp16 split
template <int W, int T>
__global__ void rmsnorm_fuse2_k(const float* __restrict__ a,
                                const float* __restrict__ wsp,
                                const float* __restrict__ x,
                                const float* __restrict__ wf,
                                float* __restrict__ hout,
                                f16* __restrict__ ohi,
                                f16* __restrict__ olo)
{
    constexpr int PER = W / T;
    const size_t row = blockIdx.x;
    const float* ar = a + row * (size_t)W;
    float vals[PER];
    float ss = 0.f;
#pragma unroll
    for (int i = 0; i < PER; i++) {
        float vv = ar[threadIdx.x + i * T];
        vv = fminf(fmaxf(vv, -10000.f), 10000.f);
        vals[i] = vv;
        ss += vv * vv;
    }
    __shared__ float red[T];
    red[threadIdx.x] = ss;
    __syncthreads();
#pragma unroll
    for (int s = T / 2; s > 0; s >>= 1) {
        if (threadIdx.x < s) red[threadIdx.x] += red[threadIdx.x + s];
        __syncthreads();
    }
    const float inv1 = 1.f / sqrtf(fmaxf(red[0] / (float)W, EPSV) + EPSV);

    float hvals[PER];
    float ss2 = 0.f;
#pragma unroll
    for (int i = 0; i < PER; i++) {
        const int c = threadIdx.x + i * T;
        float o = vals[i] * inv1 * wsp[c];
        if (!isfinite(o)) o = 0.f;
        const float hv = x[row * (size_t)W + c] + o;
        hout[row * (size_t)W + c] = hv;
        float hc = fminf(fmaxf(hv, -10000.f), 10000.f);
        hvals[i] = hc;
        ss2 += hc * hc;
    }
    __syncthreads();
    red[threadIdx.x] = ss2;
    __syncthreads();
#pragma unroll
    for (int s = T / 2; s > 0; s >>= 1) {
        if (threadIdx.x < s) red[threadIdx.x] += red[threadIdx.x + s];
        __syncthreads();
    }
    const float inv2 = 1.f / sqrtf(fmaxf(red[0] / (float)W, EPSV) + EPSV);
#pragma unroll
    for (int i = 0; i < PER; i++) {
        const int c = threadIdx.x + i * T;
        float o = hvals[i] * inv2 * wf[c];
        if (!isfinite(o)) o = 0.f;
        f16 hi, lo;
        split_h(o, hi, lo);
        ohi[row * (size_t)W + c] = hi;
        olo[row * (size_t)W + c] = lo;
    }
}

// ---------------------------------------------------------------------------
// Weight -> fp16 (single array), 8 elems/thread, row+col padded
// ---------------------------------------------------------------------------
__global__ void conv_f16_8_k(const float* __restrict__ src,
                             f16* __restrict__ dst,
                             int rows, int K0, int rowsPad, int KP)
{
    size_t i8 = ((size_t)blockIdx.x * blockDim.x + threadIdx.x) * 8;
    size_t n = (size_t)rowsPad * KP;
    if (i8 >= n) return;
    int r = (int)(i8 / KP);
    int c = (int)(i8 % KP);
    float v[8];
    if (r < rows && c + 8 <= K0) {
        const float* s = src + (size_t)r * K0 + c;
        *(float4*)&v[0] = *(const float4*)s;
        *(float4*)&v[4] = *(const float4*)(s + 4);
    } else {
#pragma unroll
        for (int i = 0; i < 8; i++) {
            int cc = c + i;
            v[i] = (r < rows && cc < K0) ? src[(size_t)r * K0 + cc] : 0.f;
        }
    }
    store8h(dst + i8, v);
}

// Interleaved w1/w3 -> fp16
__global__ void conv_ilv_f16_8_k(const float* __restrict__ w1,
                                 const float* __restrict__ w3,
                                 f16* __restrict__ dst)
{
    size_t i8 = ((size_t)blockIdx.x * blockDim.x + threadIdx.x) * 8;
    size_t n = (size_t)I2P * DD;
    if (i8 >= n) return;
    int r = (int)(i8 / DD);
    int c = (int)(i8 % DD);
    int sr = r >> 1;
    float v[8];
    if (sr < II) {
        const float* s = ((r & 1) ? w3 : w1) + (size_t)sr * DD + c;
        *(float4*)&v[0] = *(const float4*)s;
        *(float4*)&v[4] = *(const float4*)(s + 4);
    } else {
#pragma unroll
        for (int i = 0; i < 8; i++) v[i] = 0.f;
    }
    store8h(dst + i8, v);
}

// bias concat
__global__ void bias_concat_k(const float* qb, const float* kb, const float* vb,
                              const float* b1, const float* b3,
                              float* outQKV, float* outFFN)
{
    int i = blockIdx.x * blockDim.x + threadIdx.x;
    if (i < 1024) {
        outQKV[i] = qb[i];
        outQKV[1024 + i] = kb[i];
        outQKV[2048 + i] = vb[i];
    }
    if (i < I2P) {
        int sr = i >> 1;
        outFFN[i] = (sr < II) ? ((i & 1) ? b3[sr] : b1[sr]) : 0.f;
    }
}

// ---------------------------------------------------------------------------
// fp16 2-term tensor-core GEMM (NT): C = (Ah+Al) @ Bh^T + bias
// CTA 128x128, BK=32, 256 threads (8 warps 2x4, 64x32/warp), 2 CTAs/SM.
// smem: 2 stages x {Ah, Al, Bh} (SKT=40 pad). 2 MMAs per tile-pair.
// fuse_silu: interleaved (z1,z3) cols -> g=silu(z1)*z3 fp16 hi/lo split out.
// ---------------------------------------------------------------------------
#define SKT 40
#define STAGE_ELEMS (128 * SKT)
#define GEMM_SMEM (2 * 3 * STAGE_ELEMS * 2)        // 61440 bytes

__global__ void __launch_bounds__(256, 2)
gemm_f16x2(const f16* __restrict__ Ah, const f16* __restrict__ Al,
           const f16* __restrict__ Bh,
           const float* __restrict__ bias, float* __restrict__ C,
           int Mtot, int K, int ldc,
           int fuse_silu, f16* __restrict__ Ghi, f16* __restrict__ Glo,
           int ldg)
{
    extern __shared__ __align__(16) f16 smem[];

    const int tid = threadIdx.x;
    const int lane = tid & 31;
    const int wid = tid >> 5;
    const int wm = wid & 1;
    const int wn = wid >> 1;

    const int bm = blockIdx.x * 128;
    const int bn = blockIdx.y * 128;

    const int ldr = tid >> 1;
    const int ldcol = (tid & 1) * 16;

    const f16* gAh = Ah + (size_t)(bn + ldr) * K + ldcol;
    const f16* gAl = Al + (size_t)(bn + ldr) * K + ldcol;
    const bool bvalid = (bm + ldr) < Mtot;
    const f16* gBh = Bh + (size_t)(bm + ldr) * K + ldcol;

    const int s_off = ldr * SKT + ldcol;

    float acc[4][4][4];
#pragma unroll
    for (int i = 0; i < 4; i++)
#pragma unroll
        for (int j = 0; j < 4; j++)
#pragma unroll
            for (int r = 0; r < 4; r++) acc[i][j][r] = 0.f;

    const int nk = K >> 5;

    {
        f16* s = smem;
        cpa16p(s + 0 * STAGE_ELEMS + s_off,     gAh,     true);
        cpa16p(s + 0 * STAGE_ELEMS + s_off + 8, gAh + 8, true);
        cpa16p(s + 1 * STAGE_ELEMS + s_off,     gAl,     true);
        cpa16p(s + 1 * STAGE_ELEMS + s_off + 8, gAl + 8, true);
        cpa16p(s + 2 * STAGE_ELEMS + s_off,     gBh,     bvalid);
        cpa16p(s + 2 * STAGE_ELEMS + s_off + 8, gBh + 8, bvalid);
    }
    cpa_commit();

    const int a_row = wm * 64 + (lane & 15);
    const int a_colsel = ((lane >> 4) & 1) << 3;
    const int b_row0 = wn * 32 + (((lane >> 4) & 1) << 3) + (lane & 7);
    const int b_colsel = ((lane >> 3) & 1) << 3;

    for (int kt = 0; kt < nk; kt++) {
        cpa_wait_all();
        __syncthreads();

        if (kt + 1 < nk) {
            f16* s = smem + ((kt + 1) & 1) * (3 * STAGE_ELEMS);
            const int ko = (kt + 1) << 5;
            cpa16p(s + 0 * STAGE_ELEMS + s_off,     gAh + ko,     true);
            cpa16p(s + 0 * STAGE_ELEMS + s_off + 8, gAh + ko + 8, true);
            cpa16p(s + 1 * STAGE_ELEMS + s_off,     gAl + ko,     true);
            cpa16p(s + 1 * STAGE_ELEMS + s_off + 8, gAl + ko + 8, true);
            cpa16p(s + 2 * STAGE_ELEMS + s_off,     gBh + ko,     bvalid);
            cpa16p(s + 2 * STAGE_ELEMS + s_off + 8, gBh + ko + 8, bvalid);
        }
        cpa_commit();

        f16* st = smem + (kt & 1) * (3 * STAGE_ELEMS);
        const uint32_t sAh = (uint32_t)__cvta_generic_to_shared(st + 0 * STAGE_ELEMS);
        const uint32_t sAl = (uint32_t)__cvta_generic_to_shared(st + 1 * STAGE_ELEMS);
        const uint32_t sBh = (uint32_t)__cvta_generic_to_shared(st + 2 * STAGE_ELEMS);

#pragma unroll
        for (int ks = 0; ks < 2; ks++) {
            const int koff = ks * 16;
            uint32_t ah[4][4], al[4][4], bh[4][2];
#pragma unroll
            for (int mi = 0; mi < 4; mi++) {
                const uint32_t off =
                    ((a_row + mi * 16) * SKT + koff + a_colsel) * 2;
                ldm4(ah[mi], sAh + off);
                ldm4(al[mi], sAl + off);
            }
#pragma unroll
            for (int p = 0; p < 2; p++) {
                const uint32_t off =
                    ((b_row0 + p * 16) * SKT + koff + b_colsel) * 2;
                uint32_t th[4];
                ldm4(th, sBh + off);
                bh[p * 2][0] = th[0]; bh[p * 2][1] = th[1];
                bh[p * 2 + 1][0] = th[2]; bh[p * 2 + 1][1] = th[3];
            }
#pragma unroll
            for (int mi = 0; mi < 4; mi++)
#pragma unroll
                for (int ni = 0; ni < 4; ni++) {
                    mma_h(acc[mi][ni], ah[mi], bh[ni]);
                    mma_h(acc[mi][ni], al[mi], bh[ni]);
                }
        }
        __syncthreads();
    }

    const int trow = lane >> 2;
    const int tcol = (lane & 3) * 2;
    if (!fuse_silu) {
#pragma unroll
        for (int mi = 0; mi < 4; mi++) {
            const size_t r0 = (size_t)bn + wm * 64 + mi * 16 + trow;
#pragma unroll
            for (int ni = 0; ni < 4; ni++) {
                const int col = bm + wn * 32 + ni * 8 + tcol;
                if (col < Mtot) {
                    const float b0 = bias[col];
                    const float b1 = bias[col + 1];
                    float2 v0 = make_float2(acc[mi][ni][0] + b0, acc[mi][ni][1] + b1);
                    float2 v1 = make_float2(acc[mi][ni][2] + b0, acc[mi][ni][3] + b1);
                    *(float2*)&C[r0 * (size_t)ldc + col] = v0;
                    *(float2*)&C[(r0 + 8) * (size_t)ldc + col] = v1;
                }
            }
        }
    } else {
#pragma unroll
        for (int mi = 0; mi < 4; mi++) {
            const size_t r0 = (size_t)bn + wm * 64 + mi * 16 + trow;
#pragma unroll
            for (int ni = 0; ni < 4; ni++) {
                const int col = bm + wn * 32 + ni * 8 + tcol;   // even
                const int gcol = col >> 1;
                const float b0 = bias[col];
                const float b1 = bias[col + 1];
                {
                    const float z1 = acc[mi][ni][0] + b0;
                    const float z3 = acc[mi][ni][1] + b1;
                    const float g = (z1 / (1.f + expf(-z1))) * z3;
                    f16 hi, lo;
                    split_h(g, hi, lo);
                    Ghi[r0 * (size_t)ldg + gcol] = hi;
                    Glo[r0 * (size_t)ldg + gcol] = lo;
                }
                {
                    const float z1 = acc[mi][ni][2] + b0;
                    const float z3 = acc[mi][ni][3] + b1;
                    const float g = (z1 / (1.f + expf(-z1))) * z3;
                    f16 hi, lo;
                    split_h(g, hi, lo);
                    Ghi[(r0 + 8) * (size_t)ldg + gcol] = hi;
                    Glo[(r0 + 8) * (size_t)ldg + gcol] = lo;
                }
            }
        }
    }
}

// ---------------------------------------------------------------------------
// Tensor-core flash attention: QT=64 tile (2 CTAs/SM), fused q/k rmsnorm,
// bf16x3 mma internally, fp32 online softmax. Outputs fp16 hi/lo split.
// ---------------------------------------------------------------------------
#define QT 64
#define ALD 72
#define A_QH 0
#define A_QL (QT * ALD)
#define A_KH (2 * QT * ALD)
#define A_KL (3 * QT * ALD)
#define A_VH (4 * QT * ALD)
#define A_VL (5 * QT * ALD)
#define A_PH (6 * QT * ALD)
#define A_PL (7 * QT * ALD)
#define A_BF_TOT (8 * QT * ALD)
#define ATT_SMEM_BYTES (A_BF_TOT * 2 + (QT * 64 + 3 * QT) * 4)   // 90880

__global__ void __launch_bounds__(256, 2)
attn_mma_kernel(const float* __restrict__ q, const float* __restrict__ k,
                const float* __restrict__ v,
                const float* __restrict__ qnw, const float* __restrict__ knw,
                f16* __restrict__ ohi, f16* __restrict__ olo,
                const int* __restrict__ winp, int qs)
{
    extern __shared__ __align__(16) char smraw[];
    bf16* sb = (bf16*)smraw;
    float* Ss  = (float*)(smraw + A_BF_TOT * 2);
    float* m_s = Ss + QT * 64;
    float* l_s = m_s + QT;
    float* sc_s = l_s + QT;

    const int q0 = blockIdx.x * QT;
    const int h  = blockIdx.y;
    const int b  = blockIdx.z;
    const int tid = threadIdx.x;
    const int lane = tid & 31;
    const int wid = tid >> 5;
    const int wm = wid & 3;
    const int wn = wid >> 2;
    const int win = *winp;

    const uint32_t sbA = (uint32_t)__cvta_generic_to_shared(sb);

    const size_t base_q = ((size_t)(b * LL + q0)) * qs + h * HD;
    for (int i = tid; i < QT * 16; i += 256) {
        const int r = i >> 4;
        const int c4 = (i & 15) * 4;
        const float4 qv = *(const float4*)&q[base_q + (size_t)r * qs + c4];
        float vv[4] = {qv.x, qv.y, qv.z, qv.w};
#pragma unroll
        for (int j = 0; j < 4; j++) vv[j] = fminf(fmaxf(vv[j], -10000.f), 10000.f);
        float ss = vv[0] * vv[0] + vv[1] * vv[1] + vv[2] * vv[2] + vv[3] * vv[3];
        ss += __shfl_xor_sync(0xffffffffu, ss, 1);
        ss += __shfl_xor_sync(0xffffffffu, ss, 2);
        ss += __shfl_xor_sync(0xffffffffu, ss, 4);
        ss += __shfl_xor_sync(0xffffffffu, ss, 8);
        const float inv = 1.f / sqrtf(fmaxf(ss / 64.f, EPSV) + EPSV);
#pragma unroll
        for (int j = 0; j < 4; j++) {
            float o = vv[j] * inv * qnw[c4 + j];
            if (!isfinite(o)) o = 0.f;
            bf16 hi, lo;
            split_bf(o, hi, lo);
            sb[A_QH + r * ALD + c4 + j] = hi;
            sb[A_QL + r * ALD + c4 + j] = lo;
        }
    }
    if (tid < QT) { m_s[tid] = -INFINITY; l_s[tid] = 0.f; }

    float accO[4][4];
#pragma unroll
    for (int i = 0; i < 4; i++)
#pragma unroll
        for (int j = 0; j < 4; j++) accO[i][j] = 0.f;

    int lo0 = q0 - win + 1;
    if (lo0 < 0) lo0 = 0;
    const int kt0 = lo0 >> 6;
    const int kt1 = q0 >> 6;

    const int a_row = wm * 16 + (lane & 15);
    const int a_colsel = ((lane >> 4) & 1) << 3;
    const int b_row0 = wn * 32 + (((lane >> 4) & 1) << 3) + (lane & 7);
    const int b_colsel = ((lane >> 3) & 1) << 3;
    const int trow = lane >> 2;
    const int tcol = (lane & 3) * 2;
    const int r1 = wm * 16 + trow;

    __syncthreads();

    for (int kt = kt0; kt <= kt1; kt++) {
        const int j0 = kt << 6;
        const size_t base_k = ((size_t)(b * LL + j0)) * qs + h * HD;

        for (int i = tid; i < 64 * 16; i += 256) {
            const int r = i >> 4;
            const int c4 = (i & 15) * 4;
            const float4 kv = *(const float4*)&k[base_k + (size_t)r * qs + c4];
            float kk[4] = {kv.x, kv.y, kv.z, kv.w};
#pragma unroll
            for (int j = 0; j < 4; j++) kk[j] = fminf(fmaxf(kk[j], -10000.f), 10000.f);
            float ss = kk[0] * kk[0] + kk[1] * kk[1] + kk[2] * kk[2] + kk[3] * kk[3];
            ss += __shfl_xor_sync(0xffffffffu, ss, 1);
            ss += __shfl_xor_sync(0xffffffffu, ss, 2);
            ss += __shfl_xor_sync(0xffffffffu, ss, 4);
            ss += __shfl_xor_sync(0xffffffffu, ss, 8);
            const float inv = 1.f / sqrtf(fmaxf(ss / 64.f, EPSV) + EPSV);
            const float4 vvv = *(const float4*)&v[base_k + (size_t)r * qs + c4];
            const float va[4] = {vvv.x, vvv.y, vvv.z, vvv.w};
#pragma unroll
            for (int j = 0; j < 4; j++) {
                float o = kk[j] * inv * knw[c4 + j];
                if (!isfinite(o)) o = 0.f;
                bf16 hi, lo;
                split_bf(o, hi, lo);
                sb[A_KH + r * ALD + c4 + j] = hi;
                sb[A_KL + r * ALD + c4 + j] = lo;
                split_bf(va[j], hi, lo);
                sb[A_VH + (c4 + j) * ALD + r] = hi;
                sb[A_VL + (c4 + j) * ALD + r] = lo;
            }
        }
        __syncthreads();

        float accS[4][4];
#pragma unroll
        for (int i = 0; i < 4; i++)
#pragma unroll
            for (int j = 0; j < 4; j++) accS[i][j] = 0.f;

#pragma unroll
        for (int kk = 0; kk < 4; kk++) {
            uint32_t ah[4], al[4], bh[4][2], bl[4][2];
            const uint32_t aoff = (uint32_t)(a_row * ALD + kk * 16 + a_colsel) * 2;
            ldm4(ah, sbA + A_QH * 2 + aoff);
            ldm4(al, sbA + A_QL * 2 + aoff);
#pragma unroll
            for (int p = 0; p < 2; p++) {
                const uint32_t boff =
                    (uint32_t)((b_row0 + p * 16) * ALD + kk * 16 + b_colsel) * 2;
                uint32_t th[4], tl[4];
                ldm4(th, sbA + A_KH * 2 + boff);
                ldm4(tl, sbA + A_KL * 2 + boff);
                bh[p * 2][0] = th[0]; bh[p * 2][1] = th[1];
                bh[p * 2 + 1][0] = th[2]; bh[p * 2 + 1][1] = th[3];
                bl[p * 2][0] = tl[0]; bl[p * 2][1] = tl[1];
                bl[p * 2 + 1][0] = tl[2]; bl[p * 2 + 1][1] = tl[3];
            }
#pragma unroll
            for (int nt = 0; nt < 4; nt++) {
                mma_bf(accS[nt], ah, bh[nt]);
                mma_bf(accS[nt], ah, bl[nt]);
                mma_bf(accS[nt], al, bh[nt]);
            }
        }

        {
            const int qi1 = q0 + r1;
            const int qi2 = qi1 + 8;
#pragma unroll
            for (int nt = 0; nt < 4; nt++) {
                const int c = wn * 32 + nt * 8 + tcol;
                const int ja = j0 + c, jb = ja + 1;
                bool ok;
                ok = (ja <= qi1) && (qi1 - ja < win);
                Ss[r1 * 64 + c]           = ok ? accS[nt][0] * 0.125f : -INFINITY;
                ok = (jb <= qi1) && (qi1 - jb < win);
                Ss[r1 * 64 + c + 1]       = ok ? accS[nt][1] * 0.125f : -INFINITY;
                ok = (ja <= qi2) && (qi2 - ja < win);
                Ss[(r1 + 8) * 64 + c]     = ok ? accS[nt][2] * 0.125f : -INFINITY;
                ok = (jb <= qi2) && (qi2 - jb < win);
                Ss[(r1 + 8) * 64 + c + 1] = ok ? accS[nt][3] * 0.125f : -INFINITY;
            }
        }
        __syncthreads();

        {
            const int row = tid >> 2;
            const int part = tid & 3;
            float* srow = &Ss[row * 64 + part * 16];
            float tm = -INFINITY;
#pragma unroll
            for (int c = 0; c < 16; c++) tm = fmaxf(tm, srow[c]);
            tm = fmaxf(tm, __shfl_xor_sync(0xffffffffu, tm, 1));
            tm = fmaxf(tm, __shfl_xor_sync(0xffffffffu, tm, 2));

            const float mold = m_s[row];
            const float nm = fmaxf(mold, tm);
            float scale;
            float psum = 0.f;
            if (nm == -INFINITY) {
                scale = 1.f;
#pragma unroll
                for (int c = 0; c < 16; c++) srow[c] = 0.f;
            } else {
                scale = expf(mold - nm);
#pragma unroll
                for (int c = 0; c < 16; c++) {
                    const float p = expf(srow[c] - nm);
                    srow[c] = p;
                    psum += p;
                }
            }
            psum += __shfl_xor_sync(0xffffffffu, psum, 1);
            psum += __shfl_xor_sync(0xffffffffu, psum, 2);
            if (part == 0) {
                m_s[row] = nm;
                l_s[row] = l_s[row] * scale + psum;
                sc_s[row] = scale;
            }
        }
        __syncthreads();

        {
            const float s1 = sc_s[r1];
            const float s2 = sc_s[r1 + 8];
#pragma unroll
            for (int nt = 0; nt < 4; nt++) {
                accO[nt][0] *= s1; accO[nt][1] *= s1;
                accO[nt][2] *= s2; accO[nt][3] *= s2;
            }
        }
        for (int i = tid; i < QT * 16; i += 256) {
            const int r = i >> 4;
            const int c4 = (i & 15) * 4;
            const float4 pv = *(const float4*)&Ss[r * 64 + c4];
            const float pa[4] = {pv.x, pv.y, pv.z, pv.w};
#pragma unroll
            for (int j = 0; j < 4; j++) {
                bf16 hi, lo;
                split_bf(pa[j], hi, lo);
                sb[A_PH + r * ALD + c4 + j] = hi;
                sb[A_PL + r * ALD + c4 + j] = lo;
            }
        }
        __syncthreads();

#pragma unroll
        for (int kk = 0; kk < 4; kk++) {
            uint32_t ah[4], al[4], bh[4][2], bl[4][2];
            const uint32_t aoff = (uint32_t)(a_row * ALD + kk * 16 + a_colsel) * 2;
            ldm4(ah, sbA + A_PH * 2 + aoff);
            ldm4(al, sbA + A_PL * 2 + aoff);
#pragma unroll
            for (int p = 0; p < 2; p++) {
                const uint32_t boff =
                    (uint32_t)((b_row0 + p * 16) * ALD + kk * 16 + b_colsel) * 2;
                uint32_t th[4], tl[4];
                ldm4(th, sbA + A_VH * 2 + boff);
                ldm4(tl, sbA + A_VL * 2 + boff);
                bh[p * 2][0] = th[0]; bh[p * 2][1] = th[1];
                bh[p * 2 + 1][0] = th[2]; bh[p * 2 + 1][1] = th[3];
                bl[p * 2][0] = tl[0]; bl[p * 2][1] = tl[1];
                bl[p * 2 + 1][0] = tl[2]; bl[p * 2 + 1][1] = tl[3];
            }
#pragma unroll
            for (int nt = 0; nt < 4; nt++) {
                mma_bf(accO[nt], ah, bh[nt]);
                mma_bf(accO[nt], ah, bl[nt]);
                mma_bf(accO[nt], al, bh[nt]);
            }
        }
        __syncthreads();
    }

    // epilogue -> fp16 split
    {
        const float li1 = 1.f / l_s[r1];
        const float li2 = 1.f / l_s[r1 + 8];
        const size_t o1 = ((size_t)(b * LL + q0 + r1)) * DD + h * HD;
        const size_t o2 = o1 + (size_t)8 * DD;
#pragma unroll
        for (int nt = 0; nt < 4; nt++) {
            const int c = wn * 32 + nt * 8 + tcol;
            float vals[4] = {accO[nt][0] * li1, accO[nt][1] * li1,
                             accO[nt][2] * li2, accO[nt][3] * li2};
#pragma unroll
            for (int j = 0; j < 4; j++) if (!isfinite(vals[j])) vals[j] = 0.f;
            f16 hi, lo;
            split_h(vals[0], hi, lo); ohi[o1 + c] = hi;     olo[o1 + c] = lo;
            split_h(vals[1], hi, lo); ohi[o1 + c + 1] = hi; olo[o1 + c + 1] = lo;
            split_h(vals[2], hi, lo); ohi[o2 + c] = hi;     olo[o2 + c] = lo;
            split_h(vals[3], hi, lo); ohi[o2 + c + 1] = hi; olo[o2 + c + 1] = lo;
        }
    }
}

// ---------------------------------------------------------------------------
// Launch
// ---------------------------------------------------------------------------
extern "C" void kernel_launch(void* const* d_in, const int* in_sizes, int n_in,
                              void* d_out, int out_size)
{
    const float* x    = (const float*)d_in[0];
    const float* wq_w = (const float*)d_in[1];
    const float* wq_b = (const float*)d_in[2];
    const float* wk_w = (const float*)d_in[3];
    const float* wk_b = (const float*)d_in[4];
    const float* wv_w = (const float*)d_in[5];
    const float* wv_b = (const float*)d_in[6];
    const float* wo_w = (const float*)d_in[7];
    const float* wo_b = (const float*)d_in[8];
    const float* q_nw = (const float*)d_in[9];
    const float* k_nw = (const float*)d_in[10];
    const float* s_nw = (const float*)d_in[11];
    const float* sp_nw= (const float*)d_in[12];
    const float* f_nw = (const float*)d_in[13];
    const float* fp_nw= (const float*)d_in[14];
    const float* w1_w = (const float*)d_in[15];
    const float* w1_b = (const float*)d_in[16];
    const float* w2_w = (const float*)d_in[17];
    const float* w2_b = (const float*)d_in[18];
    const float* w3_w = (const float*)d_in[19];
    const float* w3_b = (const float*)d_in[20];
    const int*   winp = (const int*)d_in[21];

    float* fbase = nullptr;
    cudaGetSymbolAddress((void**)&fbase, g_scratch);
    float* qkv = fbase;                       // [4096][3072]
    float* a   = fbase + 3 * SZ_D;
    float* h   = fbase + 4 * SZ_D;
    float* f   = fbase + 5 * SZ_D;

    float* bqkv = nullptr;
    cudaGetSymbolAddress((void**)&bqkv, g_bias_qkv);
    float* bffn = nullptr;
    cudaGetSymbolAddress((void**)&bffn, g_bias_ffn);

    f16* hbase = nullptr;
    cudaGetSymbolAddress((void**)&hbase, g_hscratch);
    f16* xn_h = hbase + 0 * BSZ_ACT;
    f16* xn_l = hbase + 1 * BSZ_ACT;
    f16* at_h = hbase + 2 * BSZ_ACT;
    f16* at_l = hbase + 3 * BSZ_ACT;
    f16* hn_h = hbase + 4 * BSZ_ACT;
    f16* hn_l = hbase + 5 * BSZ_ACT;
    f16* g_h  = hbase + 6 * BSZ_ACT;
    f16* g_l  = hbase + 6 * BSZ_ACT + BSZ_G;
    f16* w_h  = hbase + 6 * BSZ_ACT + 2 * BSZ_G;

    float* out = (float*)d_out;

    cudaFuncSetAttribute(gemm_f16x2,
                         cudaFuncAttributeMaxDynamicSharedMemorySize, GEMM_SMEM);
    cudaFuncSetAttribute(attn_mma_kernel,
                         cudaFuncAttributeMaxDynamicSharedMemorySize,
                         ATT_SMEM_BYTES);

    // biases for fused GEMMs
    bias_concat_k<<<(I2P + 255) / 256, 256>>>(wq_b, wk_b, wv_b, w1_b, w3_b,
                                              bqkv, bffn);

    // 1) xn = rmsnorm(x, seq_norm_w) -> fp16 split
    rmsnorm_split_k<DD, 256><<<NROWS, 256>>>(x, s_nw, xn_h, xn_l);

    // 2) fused QKV projection
    {
        const size_t wN8 = (size_t)DD * DD / 8;
        conv_f16_8_k<<<(int)((wN8 + 255) / 256), 256>>>(wq_w, w_h, DD, DD, DD, DD);
        conv_f16_8_k<<<(int)((wN8 + 255) / 256), 256>>>(wk_w, w_h + (size_t)1024 * 1024,
                                                        DD, DD, DD, DD);
        conv_f16_8_k<<<(int)((wN8 + 255) / 256), 256>>>(wv_w, w_h + (size_t)2048 * 1024,
                                                        DD, DD, DD, DD);
        dim3 grid(QKVD / 128, NROWS / 128);
        gemm_f16x2<<<grid, 256, GEMM_SMEM>>>(xn_h, xn_l, w_h, bqkv, qkv,
                                             QKVD, DD, QKVD, 0, nullptr, nullptr, 0);
    }

    // 3) tensor-core attention (q/k rmsnorm fused) -> fp16 split output
    {
        dim3 grid(LL / QT, HH, BB);
        attn_mma_kernel<<<grid, 256, ATT_SMEM_BYTES>>>(qkv, qkv + 1024, qkv + 2048,
                                                       q_nw, k_nw,
                                                       at_h, at_l, winp, QKVD);
    }

    // 4) output projection
    {
        const size_t wN8 = (size_t)DD * DD / 8;
        conv_f16_8_k<<<(int)((wN8 + 255) / 256), 256>>>(wo_w, w_h, DD, DD, DD, DD);
        dim3 grid(DD / 128, NROWS / 128);
        gemm_f16x2<<<grid, 256, GEMM_SMEM>>>(at_h, at_l, w_h, wo_b, a,
                                             DD, DD, DD, 0, nullptr, nullptr, 0);
    }

    // 5+6) fused: h = x + rmsnorm(a, sp_nw); hn = rmsnorm(h, f_nw) split
    rmsnorm_fuse2_k<DD, 256><<<NROWS, 256>>>(a, sp_nw, x, f_nw, h, hn_h, hn_l);

    // 7) fused interleaved w1/w3 GEMM with silu epilogue -> g (fp16 split)
    {
        const size_t wN8 = (size_t)I2P * DD / 8;
        conv_ilv_f16_8_k<<<(int)((wN8 + 255) / 256), 256>>>(w1_w, w3_w, w_h);
        dim3 grid(I2P / 128, NROWS / 128);
        gemm_f16x2<<<grid, 256, GEMM_SMEM>>>(hn_h, hn_l, w_h, bffn, nullptr,
                                             I2P, DD, 0, 1, g_h, g_l, IKP);
    }

    // 8) f = g @ w2^T + b2  (K = IKP, weight K-padded)
    {
        const size_t wN8 = (size_t)DD * IKP / 8;
        conv_f16_8_k<<<(int)((wN8 + 255) / 256), 256>>>(w2_w, w_h, DD, II, DD, IKP);
        dim3 grid(DD / 128, NROWS / 128);
        gemm_f16x2<<<grid, 256, GEMM_SMEM>>>(g_h, g_l, w_h, w2_b, f,
                                             DD, IKP, DD, 0, nullptr, nullptr, 0);
    }

    // 9) out = h + rmsnorm(f, ffn_post_norm_w)
    rmsnorm_k<DD, 256><<<NROWS, 256>>>(f, fp_nw, h, out);
}

// round 17
// speedup vs baseline: 1.8606x; 1.4442x over previous
#include <cuda_runtime.h>
#include <cuda_bf16.h>
#include <cuda_fp16.h>
#include <math.h>
#include <stdint.h>

typedef __nv_bfloat16 bf16;
typedef __half f16;

// ---------------------------------------------------------------------------
// Problem constants
// ---------------------------------------------------------------------------
#define BB 4
#define LL 1024
#define DD 1024
#define HH 16
#define HD 64
#define II 3280
#define I2 6560
#define I2P 6656               // I2 padded to 128
#define IKP 3328               // II padded to 128 (w2 K / g stride)
#define QKVD 3072
#define NROWS (BB * LL)        // 4096
#define EPSV 1e-5f

#define SZ_D ((size_t)NROWS * DD)

// fp32 scratch: qkv(3*SZ_D), a, h, f
__device__ float g_scratch[6 * SZ_D];
__device__ float g_bias_qkv[QKVD];
__device__ float g_bias_ffn[I2P];

// fp16 scratch: single-precision activations + weights
#define BSZ_ACT ((size_t)NROWS * DD)
#define BSZ_G   ((size_t)NROWS * IKP)
#define BSZ_W   ((size_t)I2P * 1024)
__device__ f16 g_hscratch[3 * BSZ_ACT + BSZ_G + BSZ_W];

// ---------------------------------------------------------------------------
// helpers
// ---------------------------------------------------------------------------
__device__ __forceinline__ void split_bf(float v, bf16& hi, bf16& lo) {
    hi = __float2bfloat16(v);
    lo = __float2bfloat16(v - __bfloat162float(hi));
}

__device__ __forceinline__ void cpa16p(const void* dst, const void* src, bool valid) {
    uint32_t d = (uint32_t)__cvta_generic_to_shared(dst);
    int sz = valid ? 16 : 0;
    asm volatile("cp.async.ca.shared.global [%0], [%1], 16, %2;\n"
                 :: "r"(d), "l"(src), "r"(sz));
}
__device__ __forceinline__ void cpa_commit() {
    asm volatile("cp.async.commit_group;\n" ::: "memory");
}
__device__ __forceinline__ void cpa_wait_all() {
    asm volatile("cp.async.wait_group 0;\n" ::: "memory");
}

__device__ __forceinline__ void ldm4(uint32_t* r, uint32_t addr) {
    asm volatile("ldmatrix.sync.aligned.m8n8.x4.shared.b16 {%0,%1,%2,%3}, [%4];\n"
                 : "=r"(r[0]), "=r"(r[1]), "=r"(r[2]), "=r"(r[3]) : "r"(addr));
}

__device__ __forceinline__ void mma_h(float* d, const uint32_t* a, const uint32_t* b) {
    asm volatile(
        "mma.sync.aligned.m16n8k16.row.col.f32.f16.f16.f32 "
        "{%0,%1,%2,%3}, {%4,%5,%6,%7}, {%8,%9}, {%0,%1,%2,%3};\n"
        : "+f"(d[0]), "+f"(d[1]), "+f"(d[2]), "+f"(d[3])
        : "r"(a[0]), "r"(a[1]), "r"(a[2]), "r"(a[3]), "r"(b[0]), "r"(b[1]));
}
__device__ __forceinline__ void mma_bf(float* d, const uint32_t* a, const uint32_t* b) {
    asm volatile(
        "mma.sync.aligned.m16n8k16.row.col.f32.bf16.bf16.f32 "
        "{%0,%1,%2,%3}, {%4,%5,%6,%7}, {%8,%9}, {%0,%1,%2,%3};\n"
        : "+f"(d[0]), "+f"(d[1]), "+f"(d[2]), "+f"(d[3])
        : "r"(a[0]), "r"(a[1]), "r"(a[2]), "r"(a[3]), "r"(b[0]), "r"(b[1]));
}

__device__ __forceinline__ void store8h(f16* dst, const float* v) {
    f16 buf[8];
#pragma unroll
    for (int i = 0; i < 8; i++) buf[i] = __float2half_rn(v[i]);
    *(uint4*)dst = *(const uint4*)buf;
}

// ---------------------------------------------------------------------------
// RMSNorm (fp32 out, optional residual)
// ---------------------------------------------------------------------------
template <int W, int T>
__global__ void rmsnorm_k(const float* __restrict__ in,
                          const float* __restrict__ w,
                          const float* __restrict__ resid,
                          float* __restrict__ out)
{
    constexpr int PER = W / T;
    const size_t row = blockIdx.x;
    const float* xr = in + row * (size_t)W;
    float vals[PER];
    float ss = 0.f;
#pragma unroll
    for (int i = 0; i < PER; i++) {
        float vv = xr[threadIdx.x + i * T];
        vv = fminf(fmaxf(vv, -10000.f), 10000.f);
        vals[i] = vv;
        ss += vv * vv;
    }
    __shared__ float red[T];
    red[threadIdx.x] = ss;
    __syncthreads();
#pragma unroll
    for (int s = T / 2; s > 0; s >>= 1) {
        if (threadIdx.x < s) red[threadIdx.x] += red[threadIdx.x + s];
        __syncthreads();
    }
    const float mean = red[0] / (float)W;
    const float inv = 1.f / sqrtf(fmaxf(mean, EPSV) + EPSV);
#pragma unroll
    for (int i = 0; i < PER; i++) {
        const int c = threadIdx.x + i * T;
        float o = vals[i] * inv * w[c];
        if (!isfinite(o)) o = 0.f;
        if (resid) o += resid[row * (size_t)W + c];
        out[row * (size_t)W + c] = o;
    }
}

// RMSNorm -> single fp16
template <int W, int T>
__global__ void rmsnorm_h_k(const float* __restrict__ in,
                            const float* __restrict__ w,
                            f16* __restrict__ oh)
{
    constexpr int PER = W / T;
    const size_t row = blockIdx.x;
    const float* xr = in + row * (size_t)W;
    float vals[PER];
    float ss = 0.f;
#pragma unroll
    for (int i = 0; i < PER; i++) {
        float vv = xr[threadIdx.x + i * T];
        vv = fminf(fmaxf(vv, -10000.f), 10000.f);
        vals[i] = vv;
        ss += vv * vv;
    }
    __shared__ float red[T];
    red[threadIdx.x] = ss;
    __syncthreads();
#pragma unroll
    for (int s = T / 2; s > 0; s >>= 1) {
        if (threadIdx.x < s) red[threadIdx.x] += red[threadIdx.x + s];
        __syncthreads();
    }
    const float mean = red[0] / (float)W;
    const float inv = 1.f / sqrtf(fmaxf(mean, EPSV) + EPSV);
#pragma unroll
    for (int i = 0; i < PER; i++) {
        const int c = threadIdx.x + i * T;
        float o = vals[i] * inv * w[c];
        if (!isfinite(o)) o = 0.f;
        oh[row * (size_t)W + c] = __float2half_rn(o);
    }
}

// Fused: h = x + rmsnorm(a, wsp); hn = rmsnorm(h, wf) -> single fp16
template <int W, int T>
__global__ void rmsnorm_fuse2_k(const float* __restrict__ a,
                                const float* __restrict__ wsp,
                                const float* __restrict__ x,
                                const float* __restrict__ wf,
                                float* __restrict__ hout,
                                f16* __restrict__ oh)
{
    constexpr int PER = W / T;
    const size_t row = blockIdx.x;
    const float* ar = a + row * (size_t)W;
    float vals[PER];
    float ss = 0.f;
#pragma unroll
    for (int i = 0; i < PER; i++) {
        float vv = ar[threadIdx.x + i * T];
        vv = fminf(fmaxf(vv, -10000.f), 10000.f);
        vals[i] = vv;
        ss += vv * vv;
    }
    __shared__ float red[T];
    red[threadIdx.x] = ss;
    __syncthreads();
#pragma unroll
    for (int s = T / 2; s > 0; s >>= 1) {
        if (threadIdx.x < s) red[threadIdx.x] += red[threadIdx.x + s];
        __syncthreads();
    }
    const float inv1 = 1.f / sqrtf(fmaxf(red[0] / (float)W, EPSV) + EPSV);

    float hvals[PER];
    float ss2 = 0.f;
#pragma unroll
    for (int i = 0; i < PER; i++) {
        const int c = threadIdx.x + i * T;
        float o = vals[i] * inv1 * wsp[c];
        if (!isfinite(o)) o = 0.f;
        const float hv = x[row * (size_t)W + c] + o;
        hout[row * (size_t)W + c] = hv;
        float hc = fminf(fmaxf(hv, -10000.f), 10000.f);
        hvals[i] = hc;
        ss2 += hc * hc;
    }
    __syncthreads();
    red[threadIdx.x] = ss2;
    __syncthreads();
#pragma unroll
    for (int s = T / 2; s > 0; s >>= 1) {
        if (threadIdx.x < s) red[threadIdx.x] += red[threadIdx.x + s];
        __syncthreads();
    }
    const float inv2 = 1.f / sqrtf(fmaxf(red[0] / (float)W, EPSV) + EPSV);
#pragma unroll
    for (int i = 0; i < PER; i++) {
        const int c = threadIdx.x + i * T;
        float o = hvals[i] * inv2 * wf[c];
        if (!isfinite(o)) o = 0.f;
        oh[row * (size_t)W + c] = __float2half_rn(o);
    }
}

// ---------------------------------------------------------------------------
// Weight -> fp16, 8 elems/thread, row+col padded
// ---------------------------------------------------------------------------
__global__ void conv_f16_8_k(const float* __restrict__ src,
                             f16* __restrict__ dst,
                             int rows, int K0, int rowsPad, int KP)
{
    size_t i8 = ((size_t)blockIdx.x * blockDim.x + threadIdx.x) * 8;
    size_t n = (size_t)rowsPad * KP;
    if (i8 >= n) return;
    int r = (int)(i8 / KP);
    int c = (int)(i8 % KP);
    float v[8];
    if (r < rows && c + 8 <= K0) {
        const float* s = src + (size_t)r * K0 + c;
        *(float4*)&v[0] = *(const float4*)s;
        *(float4*)&v[4] = *(const float4*)(s + 4);
    } else {
#pragma unroll
        for (int i = 0; i < 8; i++) {
            int cc = c + i;
            v[i] = (r < rows && cc < K0) ? src[(size_t)r * K0 + cc] : 0.f;
        }
    }
    store8h(dst + i8, v);
}

// Interleaved w1/w3 -> fp16
__global__ void conv_ilv_f16_8_k(const float* __restrict__ w1,
                                 const float* __restrict__ w3,
                                 f16* __restrict__ dst)
{
    size_t i8 = ((size_t)blockIdx.x * blockDim.x + threadIdx.x) * 8;
    size_t n = (size_t)I2P * DD;
    if (i8 >= n) return;
    int r = (int)(i8 / DD);
    int c = (int)(i8 % DD);
    int sr = r >> 1;
    float v[8];
    if (sr < II) {
        const float* s = ((r & 1) ? w3 : w1) + (size_t)sr * DD + c;
        *(float4*)&v[0] = *(const float4*)s;
        *(float4*)&v[4] = *(const float4*)(s + 4);
    } else {
#pragma unroll
        for (int i = 0; i < 8; i++) v[i] = 0.f;
    }
    store8h(dst + i8, v);
}

// bias concat
__global__ void bias_concat_k(const float* qb, const float* kb, const float* vb,
                              const float* b1, const float* b3,
                              float* outQKV, float* outFFN)
{
    int i = blockIdx.x * blockDim.x + threadIdx.x;
    if (i < 1024) {
        outQKV[i] = qb[i];
        outQKV[1024 + i] = kb[i];
        outQKV[2048 + i] = vb[i];
    }
    if (i < I2P) {
        int sr = i >> 1;
        outFFN[i] = (sr < II) ? ((i & 1) ? b3[sr] : b1[sr]) : 0.f;
    }
}

// ---------------------------------------------------------------------------
// fp16 tensor-core GEMM (NT): C = A @ B^T + bias  (single-term fp16)
// CTA 128x128, BK=32, 256 threads (8 warps 2x4, 64x32/warp), 2 CTAs/SM.
// smem: 2 stages x {A, B} (SKT=40 pad). 1 MMA per tile-pair.
// fuse_silu: interleaved (z1,z3) cols -> g=silu(z1)*z3 fp16 out.
// ---------------------------------------------------------------------------
#define SKT 40
#define STAGE_ELEMS (128 * SKT)
#define GEMM_SMEM (2 * 2 * STAGE_ELEMS * 2)        // 40960 bytes

__global__ void __launch_bounds__(256, 2)
gemm_f16(const f16* __restrict__ A, const f16* __restrict__ B,
         const float* __restrict__ bias, float* __restrict__ C,
         int Mtot, int K, int ldc,
         int fuse_silu, f16* __restrict__ G, int ldg)
{
    extern __shared__ __align__(16) f16 smem[];

    const int tid = threadIdx.x;
    const int lane = tid & 31;
    const int wid = tid >> 5;
    const int wm = wid & 1;
    const int wn = wid >> 1;

    const int bm = blockIdx.x * 128;
    const int bn = blockIdx.y * 128;

    const int ldr = tid >> 1;
    const int ldcol = (tid & 1) * 16;

    const f16* gA = A + (size_t)(bn + ldr) * K + ldcol;
    const bool bvalid = (bm + ldr) < Mtot;
    const f16* gB = B + (size_t)(bm + ldr) * K + ldcol;

    const int s_off = ldr * SKT + ldcol;

    float acc[4][4][4];
#pragma unroll
    for (int i = 0; i < 4; i++)
#pragma unroll
        for (int j = 0; j < 4; j++)
#pragma unroll
            for (int r = 0; r < 4; r++) acc[i][j][r] = 0.f;

    const int nk = K >> 5;

    {
        f16* s = smem;
        cpa16p(s + 0 * STAGE_ELEMS + s_off,     gA,     true);
        cpa16p(s + 0 * STAGE_ELEMS + s_off + 8, gA + 8, true);
        cpa16p(s + 1 * STAGE_ELEMS + s_off,     gB,     bvalid);
        cpa16p(s + 1 * STAGE_ELEMS + s_off + 8, gB + 8, bvalid);
    }
    cpa_commit();

    const int a_row = wm * 64 + (lane & 15);
    const int a_colsel = ((lane >> 4) & 1) << 3;
    const int b_row0 = wn * 32 + (((lane >> 4) & 1) << 3) + (lane & 7);
    const int b_colsel = ((lane >> 3) & 1) << 3;

    for (int kt = 0; kt < nk; kt++) {
        cpa_wait_all();
        __syncthreads();

        if (kt + 1 < nk) {
            f16* s = smem + ((kt + 1) & 1) * (2 * STAGE_ELEMS);
            const int ko = (kt + 1) << 5;
            cpa16p(s + 0 * STAGE_ELEMS + s_off,     gA + ko,     true);
            cpa16p(s + 0 * STAGE_ELEMS + s_off + 8, gA + ko + 8, true);
            cpa16p(s + 1 * STAGE_ELEMS + s_off,     gB + ko,     bvalid);
            cpa16p(s + 1 * STAGE_ELEMS + s_off + 8, gB + ko + 8, bvalid);
        }
        cpa_commit();

        f16* st = smem + (kt & 1) * (2 * STAGE_ELEMS);
        const uint32_t sA = (uint32_t)__cvta_generic_to_shared(st + 0 * STAGE_ELEMS);
        const uint32_t sB = (uint32_t)__cvta_generic_to_shared(st + 1 * STAGE_ELEMS);

#pragma unroll
        for (int ks = 0; ks < 2; ks++) {
            const int koff = ks * 16;
            uint32_t ah[4][4], bh[4][2];
#pragma unroll
            for (int mi = 0; mi < 4; mi++) {
                const uint32_t off =
                    ((a_row + mi * 16) * SKT + koff + a_colsel) * 2;
                ldm4(ah[mi], sA + off);
            }
#pragma unroll
            for (int p = 0; p < 2; p++) {
                const uint32_t off =
                    ((b_row0 + p * 16) * SKT + koff + b_colsel) * 2;
                uint32_t th[4];
                ldm4(th, sB + off);
                bh[p * 2][0] = th[0]; bh[p * 2][1] = th[1];
                bh[p * 2 + 1][0] = th[2]; bh[p * 2 + 1][1] = th[3];
            }
#pragma unroll
            for (int mi = 0; mi < 4; mi++)
#pragma unroll
                for (int ni = 0; ni < 4; ni++)
                    mma_h(acc[mi][ni], ah[mi], bh[ni]);
        }
        __syncthreads();
    }

    const int trow = lane >> 2;
    const int tcol = (lane & 3) * 2;
    if (!fuse_silu) {
#pragma unroll
        for (int mi = 0; mi < 4; mi++) {
            const size_t r0 = (size_t)bn + wm * 64 + mi * 16 + trow;
#pragma unroll
            for (int ni = 0; ni < 4; ni++) {
                const int col = bm + wn * 32 + ni * 8 + tcol;
                if (col < Mtot) {
                    const float b0 = bias[col];
                    const float b1 = bias[col + 1];
                    float2 v0 = make_float2(acc[mi][ni][0] + b0, acc[mi][ni][1] + b1);
                    float2 v1 = make_float2(acc[mi][ni][2] + b0, acc[mi][ni][3] + b1);
                    *(float2*)&C[r0 * (size_t)ldc + col] = v0;
                    *(float2*)&C[(r0 + 8) * (size_t)ldc + col] = v1;
                }
            }
        }
    } else {
#pragma unroll
        for (int mi = 0; mi < 4; mi++) {
            const size_t r0 = (size_t)bn + wm * 64 + mi * 16 + trow;
#pragma unroll
            for (int ni = 0; ni < 4; ni++) {
                const int col = bm + wn * 32 + ni * 8 + tcol;   // even
                const int gcol = col >> 1;
                const float b0 = bias[col];
                const float b1 = bias[col + 1];
                {
                    const float z1 = acc[mi][ni][0] + b0;
                    const float z3 = acc[mi][ni][1] + b1;
                    const float g = (z1 / (1.f + expf(-z1))) * z3;
                    G[r0 * (size_t)ldg + gcol] = __float2half_rn(g);
                }
                {
                    const float z1 = acc[mi][ni][2] + b0;
                    const float z3 = acc[mi][ni][3] + b1;
                    const float g = (z1 / (1.f + expf(-z1))) * z3;
                    G[(r0 + 8) * (size_t)ldg + gcol] = __float2half_rn(g);
                }
            }
        }
    }
}

// ---------------------------------------------------------------------------
// Tensor-core flash attention: QT=64 tile (2 CTAs/SM), fused q/k rmsnorm,
// bf16x3 mma internally, fp32 online softmax. Outputs single fp16.
// ---------------------------------------------------------------------------
#define QT 64
#define ALD 72
#define A_QH 0
#define A_QL (QT * ALD)
#define A_KH (2 * QT * ALD)
#define A_KL (3 * QT * ALD)
#define A_VH (4 * QT * ALD)
#define A_VL (5 * QT * ALD)
#define A_PH (6 * QT * ALD)
#define A_PL (7 * QT * ALD)
#define A_BF_TOT (8 * QT * ALD)
#define ATT_SMEM_BYTES (A_BF_TOT * 2 + (QT * 64 + 3 * QT) * 4)   // 90880

__global__ void __launch_bounds__(256, 2)
attn_mma_kernel(const float* __restrict__ q, const float* __restrict__ k,
                const float* __restrict__ v,
                const float* __restrict__ qnw, const float* __restrict__ knw,
                f16* __restrict__ oh,
                const int* __restrict__ winp, int qs)
{
    extern __shared__ __align__(16) char smraw[];
    bf16* sb = (bf16*)smraw;
    float* Ss  = (float*)(smraw + A_BF_TOT * 2);
    float* m_s = Ss + QT * 64;
    float* l_s = m_s + QT;
    float* sc_s = l_s + QT;

    const int q0 = blockIdx.x * QT;
    const int h  = blockIdx.y;
    const int b  = blockIdx.z;
    const int tid = threadIdx.x;
    const int lane = tid & 31;
    const int wid = tid >> 5;
    const int wm = wid & 3;
    const int wn = wid >> 2;
    const int win = *winp;

    const uint32_t sbA = (uint32_t)__cvta_generic_to_shared(sb);

    const size_t base_q = ((size_t)(b * LL + q0)) * qs + h * HD;
    for (int i = tid; i < QT * 16; i += 256) {
        const int r = i >> 4;
        const int c4 = (i & 15) * 4;
        const float4 qv = *(const float4*)&q[base_q + (size_t)r * qs + c4];
        float vv[4] = {qv.x, qv.y, qv.z, qv.w};
#pragma unroll
        for (int j = 0; j < 4; j++) vv[j] = fminf(fmaxf(vv[j], -10000.f), 10000.f);
        float ss = vv[0] * vv[0] + vv[1] * vv[1] + vv[2] * vv[2] + vv[3] * vv[3];
        ss += __shfl_xor_sync(0xffffffffu, ss, 1);
        ss += __shfl_xor_sync(0xffffffffu, ss, 2);
        ss += __shfl_xor_sync(0xffffffffu, ss, 4);
        ss += __shfl_xor_sync(0xffffffffu, ss, 8);
        const float inv = 1.f / sqrtf(fmaxf(ss / 64.f, EPSV) + EPSV);
#pragma unroll
        for (int j = 0; j < 4; j++) {
            float o = vv[j] * inv * qnw[c4 + j];
            if (!isfinite(o)) o = 0.f;
            bf16 hi, lo;
            split_bf(o, hi, lo);
            sb[A_QH + r * ALD + c4 + j] = hi;
            sb[A_QL + r * ALD + c4 + j] = lo;
        }
    }
    if (tid < QT) { m_s[tid] = -INFINITY; l_s[tid] = 0.f; }

    float accO[4][4];
#pragma unroll
    for (int i = 0; i < 4; i++)
#pragma unroll
        for (int j = 0; j < 4; j++) accO[i][j] = 0.f;

    int lo0 = q0 - win + 1;
    if (lo0 < 0) lo0 = 0;
    const int kt0 = lo0 >> 6;
    const int kt1 = q0 >> 6;

    const int a_row = wm * 16 + (lane & 15);
    const int a_colsel = ((lane >> 4) & 1) << 3;
    const int b_row0 = wn * 32 + (((lane >> 4) & 1) << 3) + (lane & 7);
    const int b_colsel = ((lane >> 3) & 1) << 3;
    const int trow = lane >> 2;
    const int tcol = (lane & 3) * 2;
    const int r1 = wm * 16 + trow;

    __syncthreads();

    for (int kt = kt0; kt <= kt1; kt++) {
        const int j0 = kt << 6;
        const size_t base_k = ((size_t)(b * LL + j0)) * qs + h * HD;

        for (int i = tid; i < 64 * 16; i += 256) {
            const int r = i >> 4;
            const int c4 = (i & 15) * 4;
            const float4 kv = *(const float4*)&k[base_k + (size_t)r * qs + c4];
            float kk[4] = {kv.x, kv.y, kv.z, kv.w};
#pragma unroll
            for (int j = 0; j < 4; j++) kk[j] = fminf(fmaxf(kk[j], -10000.f), 10000.f);
            float ss = kk[0] * kk[0] + kk[1] * kk[1] + kk[2] * kk[2] + kk[3] * kk[3];
            ss += __shfl_xor_sync(0xffffffffu, ss, 1);
            ss += __shfl_xor_sync(0xffffffffu, ss, 2);
            ss += __shfl_xor_sync(0xffffffffu, ss, 4);
            ss += __shfl_xor_sync(0xffffffffu, ss, 8);
            const float inv = 1.f / sqrtf(fmaxf(ss / 64.f, EPSV) + EPSV);
            const float4 vvv = *(const float4*)&v[base_k + (size_t)r * qs + c4];
            const float va[4] = {vvv.x, vvv.y, vvv.z, vvv.w};
#pragma unroll
            for (int j = 0; j < 4; j++) {
                float o = kk[j] * inv * knw[c4 + j];
                if (!isfinite(o)) o = 0.f;
                bf16 hi, lo;
                split_bf(o, hi, lo);
                sb[A_KH + r * ALD + c4 + j] = hi;
                sb[A_KL + r * ALD + c4 + j] = lo;
                split_bf(va[j], hi, lo);
                sb[A_VH + (c4 + j) * ALD + r] = hi;
                sb[A_VL + (c4 + j) * ALD + r] = lo;
            }
        }
        __syncthreads();

        float accS[4][4];
#pragma unroll
        for (int i = 0; i < 4; i++)
#pragma unroll
            for (int j = 0; j < 4; j++) accS[i][j] = 0.f;

#pragma unroll
        for (int kk = 0; kk < 4; kk++) {
            uint32_t ah[4], al[4], bh[4][2], bl[4][2];
            const uint32_t aoff = (uint32_t)(a_row * ALD + kk * 16 + a_colsel) * 2;
            ldm4(ah, sbA + A_QH * 2 + aoff);
            ldm4(al, sbA + A_QL * 2 + aoff);
#pragma unroll
            for (int p = 0; p < 2; p++) {
                const uint32_t boff =
                    (uint32_t)((b_row0 + p * 16) * ALD + kk * 16 + b_colsel) * 2;
                uint32_t th[4], tl[4];
                ldm4(th, sbA + A_KH * 2 + boff);
                ldm4(tl, sbA + A_KL * 2 + boff);
                bh[p * 2][0] = th[0]; bh[p * 2][1] = th[1];
                bh[p * 2 + 1][0] = th[2]; bh[p * 2 + 1][1] = th[3];
                bl[p * 2][0] = tl[0]; bl[p * 2][1] = tl[1];
                bl[p * 2 + 1][0] = tl[2]; bl[p * 2 + 1][1] = tl[3];
            }
#pragma unroll
            for (int nt = 0; nt < 4; nt++) {
                mma_bf(accS[nt], ah, bh[nt]);
                mma_bf(accS[nt], ah, bl[nt]);
                mma_bf(accS[nt], al, bh[nt]);
            }
        }

        {
            const int qi1 = q0 + r1;
            const int qi2 = qi1 + 8;
#pragma unroll
            for (int nt = 0; nt < 4; nt++) {
                const int c = wn * 32 + nt * 8 + tcol;
                const int ja = j0 + c, jb = ja + 1;
                bool ok;
                ok = (ja <= qi1) && (qi1 - ja < win);
                Ss[r1 * 64 + c]           = ok ? accS[nt][0] * 0.125f : -INFINITY;
                ok = (jb <= qi1) && (qi1 - jb < win);
                Ss[r1 * 64 + c + 1]       = ok ? accS[nt][1] * 0.125f : -INFINITY;
                ok = (ja <= qi2) && (qi2 - ja < win);
                Ss[(r1 + 8) * 64 + c]     = ok ? accS[nt][2] * 0.125f : -INFINITY;
                ok = (jb <= qi2) && (qi2 - jb < win);
                Ss[(r1 + 8) * 64 + c + 1] = ok ? accS[nt][3] * 0.125f : -INFINITY;
            }
        }
        __syncthreads();

        {
            const int row = tid >> 2;
            const int part = tid & 3;
            float* srow = &Ss[row * 64 + part * 16];
            float tm = -INFINITY;
#pragma unroll
            for (int c = 0; c < 16; c++) tm = fmaxf(tm, srow[c]);
            tm = fmaxf(tm, __shfl_xor_sync(0xffffffffu, tm, 1));
            tm = fmaxf(tm, __shfl_xor_sync(0xffffffffu, tm, 2));

            const float mold = m_s[row];
            const float nm = fmaxf(mold, tm);
            float scale;
            float psum = 0.f;
            if (nm == -INFINITY) {
                scale = 1.f;
#pragma unroll
                for (int c = 0; c < 16; c++) srow[c] = 0.f;
            } else {
                scale = expf(mold - nm);
#pragma unroll
                for (int c = 0; c < 16; c++) {
                    const float p = expf(srow[c] - nm);
                    srow[c] = p;
                    psum += p;
                }
            }
            psum += __shfl_xor_sync(0xffffffffu, psum, 1);
            psum += __shfl_xor_sync(0xffffffffu, psum, 2);
            if (part == 0) {
                m_s[row] = nm;
                l_s[row] = l_s[row] * scale + psum;
                sc_s[row] = scale;
            }
        }
        __syncthreads();

        {
            const float s1 = sc_s[r1];
            const float s2 = sc_s[r1 + 8];
#pragma unroll
            for (int nt = 0; nt < 4; nt++) {
                accO[nt][0] *= s1; accO[nt][1] *= s1;
                accO[nt][2] *= s2; accO[nt][3] *= s2;
            }
        }
        for (int i = tid; i < QT * 16; i += 256) {
            const int r = i >> 4;
            const int c4 = (i & 15) * 4;
            const float4 pv = *(const float4*)&Ss[r * 64 + c4];
            const float pa[4] = {pv.x, pv.y, pv.z, pv.w};
#pragma unroll
            for (int j = 0; j < 4; j++) {
                bf16 hi, lo;
                split_bf(pa[j], hi, lo);
                sb[A_PH + r * ALD + c4 + j] = hi;
                sb[A_PL + r * ALD + c4 + j] = lo;
            }
        }
        __syncthreads();

#pragma unroll
        for (int kk = 0; kk < 4; kk++) {
            uint32_t ah[4], al[4], bh[4][2], bl[4][2];
            const uint32_t aoff = (uint32_t)(a_row * ALD + kk * 16 + a_colsel) * 2;
            ldm4(ah, sbA + A_PH * 2 + aoff);
            ldm4(al, sbA + A_PL * 2 + aoff);
#pragma unroll
            for (int p = 0; p < 2; p++) {
                const uint32_t boff =
                    (uint32_t)((b_row0 + p * 16) * ALD + kk * 16 + b_colsel) * 2;
                uint32_t th[4], tl[4];
                ldm4(th, sbA + A_VH * 2 + boff);
                ldm4(tl, sbA + A_VL * 2 + boff);
                bh[p * 2][0] = th[0]; bh[p * 2][1] = th[1];
                bh[p * 2 + 1][0] = th[2]; bh[p * 2 + 1][1] = th[3];
                bl[p * 2][0] = tl[0]; bl[p * 2][1] = tl[1];
                bl[p * 2 + 1][0] = tl[2]; bl[p * 2 + 1][1] = tl[3];
            }
#pragma unroll
            for (int nt = 0; nt < 4; nt++) {
                mma_bf(accO[nt], ah, bh[nt]);
                mma_bf(accO[nt], ah, bl[nt]);
                mma_bf(accO[nt], al, bh[nt]);
            }
        }
        __syncthreads();
    }

    // epilogue -> single fp16
    {
        const float li1 = 1.f / l_s[r1];
        const float li2 = 1.f / l_s[r1 + 8];
        const size_t o1 = ((size_t)(b * LL + q0 + r1)) * DD + h * HD;
        const size_t o2 = o1 + (size_t)8 * DD;
#pragma unroll
        for (int nt = 0; nt < 4; nt++) {
            const int c = wn * 32 + nt * 8 + tcol;
            float vals[4] = {accO[nt][0] * li1, accO[nt][1] * li1,
                             accO[nt][2] * li2, accO[nt][3] * li2};
#pragma unroll
            for (int j = 0; j < 4; j++) if (!isfinite(vals[j])) vals[j] = 0.f;
            oh[o1 + c]     = __float2half_rn(vals[0]);
            oh[o1 + c + 1] = __float2half_rn(vals[1]);
            oh[o2 + c]     = __float2half_rn(vals[2]);
            oh[o2 + c + 1] = __float2half_rn(vals[3]);
        }
    }
}

// ---------------------------------------------------------------------------
// Launch
// ---------------------------------------------------------------------------
extern "C" void kernel_launch(void* const* d_in, const int* in_sizes, int n_in,
                              void* d_out, int out_size)
{
    const float* x    = (const float*)d_in[0];
    const float* wq_w = (const float*)d_in[1];
    const float* wq_b = (const float*)d_in[2];
    const float* wk_w = (const float*)d_in[3];
    const float* wk_b = (const float*)d_in[4];
    const float* wv_w = (const float*)d_in[5];
    const float* wv_b = (const float*)d_in[6];
    const float* wo_w = (const float*)d_in[7];
    const float* wo_b = (const float*)d_in[8];
    const float* q_nw = (const float*)d_in[9];
    const float* k_nw = (const float*)d_in[10];
    const float* s_nw = (const float*)d_in[11];
    const float* sp_nw= (const float*)d_in[12];
    const float* f_nw = (const float*)d_in[13];
    const float* fp_nw= (const float*)d_in[14];
    const float* w1_w = (const float*)d_in[15];
    const float* w1_b = (const float*)d_in[16];
    const float* w2_w = (const float*)d_in[17];
    const float* w2_b = (const float*)d_in[18];
    const float* w3_w = (const float*)d_in[19];
    const float* w3_b = (const float*)d_in[20];
    const int*   winp = (const int*)d_in[21];

    float* fbase = nullptr;
    cudaGetSymbolAddress((void**)&fbase, g_scratch);
    float* qkv = fbase;                       // [4096][3072]
    float* a   = fbase + 3 * SZ_D;
    float* h   = fbase + 4 * SZ_D;
    float* f   = fbase + 5 * SZ_D;

    float* bqkv = nullptr;
    cudaGetSymbolAddress((void**)&bqkv, g_bias_qkv);
    float* bffn = nullptr;
    cudaGetSymbolAddress((void**)&bffn, g_bias_ffn);

    f16* hbase = nullptr;
    cudaGetSymbolAddress((void**)&hbase, g_hscratch);
    f16* xn_h = hbase + 0 * BSZ_ACT;
    f16* at_h = hbase + 1 * BSZ_ACT;
    f16* hn_h = hbase + 2 * BSZ_ACT;
    f16* g_h  = hbase + 3 * BSZ_ACT;
    f16* w_h  = hbase + 3 * BSZ_ACT + BSZ_G;

    float* out = (float*)d_out;

    cudaFuncSetAttribute(gemm_f16,
                         cudaFuncAttributeMaxDynamicSharedMemorySize, GEMM_SMEM);
    cudaFuncSetAttribute(attn_mma_kernel,
                         cudaFuncAttributeMaxDynamicSharedMemorySize,
                         ATT_SMEM_BYTES);

    // biases for fused GEMMs
    bias_concat_k<<<(I2P + 255) / 256, 256>>>(wq_b, wk_b, wv_b, w1_b, w3_b,
                                              bqkv, bffn);

    // 1) xn = rmsnorm(x, seq_norm_w) -> fp16
    rmsnorm_h_k<DD, 256><<<NROWS, 256>>>(x, s_nw, xn_h);

    // 2) fused QKV projection
    {
        const size_t wN8 = (size_t)DD * DD / 8;
        conv_f16_8_k<<<(int)((wN8 + 255) / 256), 256>>>(wq_w, w_h, DD, DD, DD, DD);
        conv_f16_8_k<<<(int)((wN8 + 255) / 256), 256>>>(wk_w, w_h + (size_t)1024 * 1024,
                                                        DD, DD, DD, DD);
        conv_f16_8_k<<<(int)((wN8 + 255) / 256), 256>>>(wv_w, w_h + (size_t)2048 * 1024,
                                                        DD, DD, DD, DD);
        dim3 grid(QKVD / 128, NROWS / 128);
        gemm_f16<<<grid, 256, GEMM_SMEM>>>(xn_h, w_h, bqkv, qkv,
                                           QKVD, DD, QKVD, 0, nullptr, 0);
    }

    // 3) tensor-core attention (q/k rmsnorm fused) -> fp16 output
    {
        dim3 grid(LL / QT, HH, BB);
        attn_mma_kernel<<<grid, 256, ATT_SMEM_BYTES>>>(qkv, qkv + 1024, qkv + 2048,
                                                       q_nw, k_nw,
                                                       at_h, winp, QKVD);
    }

    // 4) output projection
    {
        const size_t wN8 = (size_t)DD * DD / 8;
        conv_f16_8_k<<<(int)((wN8 + 255) / 256), 256>>>(wo_w, w_h, DD, DD, DD, DD);
        dim3 grid(DD / 128, NROWS / 128);
        gemm_f16<<<grid, 256, GEMM_SMEM>>>(at_h, w_h, wo_b, a,
                                           DD, DD, DD, 0, nullptr, 0);
    }

    // 5+6) fused: h = x + rmsnorm(a, sp_nw); hn = rmsnorm(h, f_nw) -> fp16
    rmsnorm_fuse2_k<DD, 256><<<NROWS, 256>>>(a, sp_nw, x, f_nw, h, hn_h);

    // 7) fused interleaved w1/w3 GEMM with silu epilogue -> g (fp16)
    {
        const size_t wN8 = (size_t)I2P * DD / 8;
        conv_ilv_f16_8_k<<<(int)((wN8 + 255) / 256), 256>>>(w1_w, w3_w, w_h);
        dim3 grid(I2P / 128, NROWS / 128);
        gemm_f16<<<grid, 256, GEMM_SMEM>>>(hn_h, w_h, bffn, nullptr,
                                           I2P, DD, 0, 1, g_h, IKP);
    }

    // 8) f = g @ w2^T + b2  (K = IKP, weight K-padded)
    {
        const size_t wN8 = (size_t)DD * IKP / 8;
        conv_f16_8_k<<<(int)((wN8 + 255) / 256), 256>>>(w2_w, w_h, DD, II, DD, IKP);
        dim3 grid(DD / 128, NROWS / 128);
        gemm_f16<<<grid, 256, GEMM_SMEM>>>(g_h, w_h, w2_b, f,
                                           DD, IKP, DD, 0, nullptr, 0);
    }

    // 9) out = h + rmsnorm(f, ffn_post_norm_w)
    rmsnorm_k<DD, 256><<<NROWS, 256>>>(f, fp_nw, h, out);
}